// round 8
// baseline (speedup 1.0000x reference)
#include <cuda_runtime.h>
#include <math.h>
#include <float.h>
#include <stdint.h>

#define N_NODES 8192
#define HID 256
#define NCLS 5
#define TOPK 11   // K+1
#define SSTR 20   // smem row stride in uint32 (bf16-pair) units; 16 pairs + 4 pad
#define NH (N_NODES * HID)

// ---------------- scratch (static device globals; no allocation) ----------------
__device__ float g_sim[(size_t)N_NODES * N_NODES];   // 256 MB (reused per modality)
__device__ float g_t[3 * NH];
__device__ float g_feat[3 * NH];
__device__ float g_fn[3 * NH];
__device__ float g_h[3 * NH];
__device__ float g_part[3 * 2 * 64 * HID];
__device__ float g_bna[3 * HID];
__device__ float g_bnc[3 * HID];
__device__ int   g_adj_idx[3 * N_NODES * TOPK];
__device__ float g_adj_w[3 * N_NODES * TOPK];
__device__ float g_logits[3 * N_NODES * NCLS];

// pack two floats to bf16x2 (low = x, high = y), round-to-nearest
__device__ __forceinline__ uint32_t pack_bf16(float x, float y)
{
    uint32_t r;
    asm("cvt.rn.bf16x2.f32 %0, %1, %2;" : "=r"(r) : "f"(y), "f"(x));
    return r;
}
__device__ __forceinline__ float bf16lo_f(uint32_t p) { return __uint_as_float(p << 16); }
__device__ __forceinline__ float bf16hi_f(uint32_t p) { return __uint_as_float(p & 0xFFFF0000u); }

__device__ __forceinline__ void split4(float4 v, uint32_t& h0, uint32_t& h1,
                                       uint32_t& l0, uint32_t& l1)
{
    h0 = pack_bf16(v.x, v.y);
    h1 = pack_bf16(v.z, v.w);
    l0 = pack_bf16(v.x - bf16lo_f(h0), v.y - bf16hi_f(h0));
    l1 = pack_bf16(v.z - bf16lo_f(h1), v.w - bf16hi_f(h1));
}

#define MMA_BF16(C, A, B) \
    asm volatile( \
        "mma.sync.aligned.m16n8k16.row.col.f32.bf16.bf16.f32 " \
        "{%0,%1,%2,%3}, {%4,%5,%6,%7}, {%8,%9}, {%0,%1,%2,%3};\n" \
        : "+f"((C)[0]), "+f"((C)[1]), "+f"((C)[2]), "+f"((C)[3]) \
        : "r"((A)[0]), "r"((A)[1]), "r"((A)[2]), "r"((A)[3]), \
          "r"((B)[0]), "r"((B)[1]))

#define LDSM_X4(r0, r1, r2, r3, addr) \
    asm volatile("ldmatrix.sync.aligned.m8n8.x4.shared.b16 {%0,%1,%2,%3}, [%4];" \
        : "=r"(r0), "=r"(r1), "=r"(r2), "=r"(r3) : "r"(addr))

__device__ __forceinline__ uint32_t smem_u32(const void* p)
{
    return (uint32_t)__cvta_generic_to_shared(p);
}

// ---------------- bf16x3 split-precision tensor-core GEMM ------------------------
// C[M,N] = A[M,K] * op(B) (+bias,+relu).  Dekker split: Ahi*Bhi + Ahi*Blo + Alo*Bhi.
// TRANSB=true : B is [N,K] row-major (C = A * B^T); false: B is [K,N].
// VEC4: static float4 A/B loads; otherwise runtime (K%4==0) enables vec4.
// SYMM: A==B, C symmetric, linear grid over lower-tri tiles, off-diag mirrored.
// ENC : per-z (A,B,K) selection from (A,K),(A1,K1),(A2,K2) for the 3 encoders.
// Batched over blockIdx.z via zs* strides. ldmatrix fragments + register prefetch.
template<bool TRANSB, bool BIAS_RELU, bool VEC4, bool SYMM, bool ENC>
__global__ __launch_bounds__(256) void gemm_bf16x3(const float* __restrict__ A,
                                                   const float* __restrict__ B,
                                                   const float* __restrict__ bias,
                                                   float* __restrict__ C,
                                                   int M, int N, int K,
                                                   int zsA, int zsB, int zsBias, int zsC,
                                                   const float* A1, const float* B1, int K1,
                                                   const float* A2, const float* B2, int K2)
{
    __shared__ uint32_t sAhi[128 * SSTR];
    __shared__ uint32_t sAlo[128 * SSTR];
    __shared__ uint32_t sBhi[128 * SSTR];
    __shared__ uint32_t sBlo[128 * SSTR];

    if (ENC) {
        if (blockIdx.z == 1) { A = A1; B = B1; K = K1; }
        else if (blockIdx.z == 2) { A = A2; B = B2; K = K2; }
    } else {
        A += (size_t)blockIdx.z * zsA;
        B += (size_t)blockIdx.z * zsB;
    }
    if (BIAS_RELU) bias += (size_t)blockIdx.z * zsBias;
    C += (size_t)blockIdx.z * zsC;

    const bool v4 = VEC4 || ((K & 3) == 0);

    const int tid  = threadIdx.x;
    const int lane = tid & 31;
    const int warp = tid >> 5;
    const int gid  = lane >> 2;
    const int tig  = lane & 3;
    const int wm   = warp >> 2;     // 0..1 -> m offset wm*64
    const int wn   = warp & 3;      // 0..3 -> n offset wn*32

    int mo, no;
    bool mirror = false;
    if (SYMM) {
        int t = blockIdx.x;
        int bi = (int)((sqrtf(8.f * (float)t + 1.f) - 1.f) * 0.5f);
        while ((bi + 1) * (bi + 2) / 2 <= t) bi++;
        while (bi * (bi + 1) / 2 > t) bi--;
        int bj = t - bi * (bi + 1) / 2;
        mo = bi * 128; no = bj * 128;
        mirror = (bi != bj);
    } else {
        mo = blockIdx.y * 128;
        no = blockIdx.x * 128;
    }

    float acc[4][4][4];
#pragma unroll
    for (int i = 0; i < 4; i++)
#pragma unroll
        for (int j = 0; j < 4; j++)
#pragma unroll
            for (int q = 0; q < 4; q++) acc[i][j][q] = 0.f;

    // ldmatrix lane address components (bytes)
    const uint32_t aoff = (uint32_t)((wm * 64 + (lane & 7) + ((lane >> 3) & 1) * 8) * (SSTR * 4)
                                     + ((lane >> 4) & 1) * 16);
    const uint32_t boff = (uint32_t)((wn * 32 + (lane & 7) + ((lane >> 4) & 1) * 8) * (SSTR * 4)
                                     + ((lane >> 3) & 1) * 16);
    const uint32_t baseAhi = smem_u32(sAhi), baseAlo = smem_u32(sAlo);
    const uint32_t baseBhi = smem_u32(sBhi), baseBlo = smem_u32(sBlo);

    auto loadA = [&](int ko, int u) -> float4 {
        int f = u * 256 + tid;
        int r = f >> 3, kq = f & 7;
        int gk = ko + kq * 4;
        float4 v;
        if (v4 && gk + 3 < K) {
            v = *reinterpret_cast<const float4*>(&A[(size_t)(mo + r) * K + gk]);
        } else {
            const float* p = &A[(size_t)(mo + r) * K];
            v.x = (gk + 0 < K) ? p[gk + 0] : 0.f;
            v.y = (gk + 1 < K) ? p[gk + 1] : 0.f;
            v.z = (gk + 2 < K) ? p[gk + 2] : 0.f;
            v.w = (gk + 3 < K) ? p[gk + 3] : 0.f;
        }
        return v;
    };
    auto loadB = [&](int ko, int u) -> float4 {
        float4 v;
        if (TRANSB) {
            int f = u * 256 + tid;
            int r = f >> 3, kq = f & 7;
            int gk = ko + kq * 4;
            if (v4 && gk + 3 < K) {
                v = *reinterpret_cast<const float4*>(&B[(size_t)(no + r) * K + gk]);
            } else {
                const float* p = &B[(size_t)(no + r) * K];
                v.x = (gk + 0 < K) ? p[gk + 0] : 0.f;
                v.y = (gk + 1 < K) ? p[gk + 1] : 0.f;
                v.z = (gk + 2 < K) ? p[gk + 2] : 0.f;
                v.w = (gk + 3 < K) ? p[gk + 3] : 0.f;
            }
        } else {
            int f = u * 256 + tid;
            int n = f & 127;
            int kq = f >> 7;
            int gk = ko + kq * 4;
            v.x = (gk + 0 < K) ? B[(size_t)(gk + 0) * N + no + n] : 0.f;
            v.y = (gk + 1 < K) ? B[(size_t)(gk + 1) * N + no + n] : 0.f;
            v.z = (gk + 2 < K) ? B[(size_t)(gk + 2) * N + no + n] : 0.f;
            v.w = (gk + 3 < K) ? B[(size_t)(gk + 3) * N + no + n] : 0.f;
        }
        return v;
    };

    float4 va[4], vb[4];
#pragma unroll
    for (int u = 0; u < 4; u++) { va[u] = loadA(0, u); vb[u] = loadB(0, u); }

    for (int ko = 0; ko < K; ko += 32) {
#pragma unroll
        for (int u = 0; u < 4; u++) {
            int f = u * 256 + tid;
            uint32_t h0, h1, l0, l1;
            {   // A: [row][pair]
                int r = f >> 3, kq = f & 7;
                split4(va[u], h0, h1, l0, l1);
                int w = r * SSTR + kq * 2;
                sAhi[w] = h0; sAhi[w + 1] = h1;
                sAlo[w] = l0; sAlo[w + 1] = l1;
            }
            {   // B: [n][pair]
                int r, kq;
                if (TRANSB) { r = f >> 3; kq = f & 7; }
                else        { r = f & 127; kq = f >> 7; }
                split4(vb[u], h0, h1, l0, l1);
                int w = r * SSTR + kq * 2;
                sBhi[w] = h0; sBhi[w + 1] = h1;
                sBlo[w] = l0; sBlo[w + 1] = l1;
            }
        }
        __syncthreads();

        const int kn = ko + 32;
        if (kn < K) {
#pragma unroll
            for (int u = 0; u < 4; u++) { va[u] = loadA(kn, u); vb[u] = loadB(kn, u); }
        }

#pragma unroll
        for (int ks = 0; ks < 2; ks++) {
            const uint32_t kb = (uint32_t)(ks * 32);
            uint32_t bhi[4][2], blo[4][2];
#pragma unroll
            for (int p = 0; p < 2; p++) {
                LDSM_X4(bhi[2 * p][0], bhi[2 * p][1], bhi[2 * p + 1][0], bhi[2 * p + 1][1],
                        baseBhi + boff + (uint32_t)(p * 16 * SSTR * 4) + kb);
                LDSM_X4(blo[2 * p][0], blo[2 * p][1], blo[2 * p + 1][0], blo[2 * p + 1][1],
                        baseBlo + boff + (uint32_t)(p * 16 * SSTR * 4) + kb);
            }
#pragma unroll
            for (int i = 0; i < 4; i++) {
                uint32_t ahi[4], alo[4];
                LDSM_X4(ahi[0], ahi[1], ahi[2], ahi[3],
                        baseAhi + aoff + (uint32_t)(i * 16 * SSTR * 4) + kb);
                LDSM_X4(alo[0], alo[1], alo[2], alo[3],
                        baseAlo + aoff + (uint32_t)(i * 16 * SSTR * 4) + kb);
#pragma unroll
                for (int j = 0; j < 4; j++) {
                    MMA_BF16(acc[i][j], ahi, bhi[j]);
                    MMA_BF16(acc[i][j], ahi, blo[j]);
                    MMA_BF16(acc[i][j], alo, bhi[j]);
                }
            }
        }
        __syncthreads();
    }

    // ---- epilogue
#pragma unroll
    for (int i = 0; i < 4; i++) {
        const int r0 = mo + wm * 64 + i * 16 + gid;
#pragma unroll
        for (int j = 0; j < 4; j++) {
            const int c = no + wn * 32 + j * 8 + tig * 2;
            float v0 = acc[i][j][0], v1 = acc[i][j][1];
            float v2 = acc[i][j][2], v3 = acc[i][j][3];
            if (BIAS_RELU) {
                const float b0 = bias[c], b1 = bias[c + 1];
                v0 = fmaxf(v0 + b0, 0.f); v1 = fmaxf(v1 + b1, 0.f);
                v2 = fmaxf(v2 + b0, 0.f); v3 = fmaxf(v3 + b1, 0.f);
            }
            *reinterpret_cast<float2*>(&C[(size_t)r0 * N + c])       = make_float2(v0, v1);
            *reinterpret_cast<float2*>(&C[(size_t)(r0 + 8) * N + c]) = make_float2(v2, v3);
            if (SYMM && mirror) {
                C[(size_t)c * N + r0]           = v0;
                C[(size_t)(c + 1) * N + r0]     = v1;
                C[(size_t)c * N + r0 + 8]       = v2;
                C[(size_t)(c + 1) * N + r0 + 8] = v3;
            }
        }
    }
}

// ---------------- BatchNorm stats (two stage, deterministic, z-batched) ----------
__global__ void bn_colpart(void)
{
    const int z = blockIdx.z;
    const float* t = g_t + (size_t)z * NH;
    float* part = g_part + (size_t)z * 2 * 64 * HID;
    const int c = threadIdx.x;
    const int r0 = blockIdx.x * 128;
    float s = 0.f, s2 = 0.f;
    for (int r = r0; r < r0 + 128; r++) {
        float v = t[(size_t)r * HID + c];
        s += v; s2 += v * v;
    }
    part[blockIdx.x * HID + c] = s;
    part[64 * HID + blockIdx.x * HID + c] = s2;
}

__global__ void bn_colfinal(const float* __restrict__ gam, const float* __restrict__ bet)
{
    const int z = blockIdx.z;
    const float* part = g_part + (size_t)z * 2 * 64 * HID;
    const int c = threadIdx.x;
    float s = 0.f, s2 = 0.f;
    for (int b = 0; b < 64; b++) {
        s  += part[b * HID + c];
        s2 += part[64 * HID + b * HID + c];
    }
    const float mu = s * (1.f / N_NODES);
    float var = s2 * (1.f / N_NODES) - mu * mu;
    const float a = gam[z * HID + c] * rsqrtf(var + 1e-5f);
    g_bna[z * HID + c] = a;
    g_bnc[z * HID + c] = bet[z * HID + c] - mu * a;
}

__global__ __launch_bounds__(256) void bn_apply_rownorm(void)
{
    const int z = blockIdx.z;
    const float* t = g_t + (size_t)z * NH;
    float* feat = g_feat + (size_t)z * NH;
    float* fn   = g_fn   + (size_t)z * NH;
    const int tid = threadIdx.x;
    const int warp = tid >> 5, lane = tid & 31;
    const int row = blockIdx.x * 8 + warp;
    float v[8];
    float sq = 0.f;
#pragma unroll
    for (int u = 0; u < 8; u++) {
        int c = lane + 32 * u;
        float x = g_bna[z * HID + c] * t[(size_t)row * HID + c] + g_bnc[z * HID + c];
        v[u] = x; sq += x * x;
    }
#pragma unroll
    for (int s = 16; s; s >>= 1) sq += __shfl_xor_sync(0xffffffffu, sq, s);
    const float norm = sqrtf(sq);
    const float inv = 1.f / fmaxf(norm, 1e-12f);
#pragma unroll
    for (int u = 0; u < 8; u++) {
        int c = lane + 32 * u;
        feat[(size_t)row * HID + c] = v[u];
        fn[(size_t)row * HID + c]   = v[u] * inv;
    }
}

// ---------------- top-(K+1) per row + sparse adjacency build ----------------------
// Hierarchical shuffle merge: per-thread sorted lists -> intra-warp argmax rounds
// (no barriers) -> one __syncthreads -> warp 0 merges the 8 warp lists.
// Tie-break everywhere: higher value wins; equal value -> lower index wins.
__global__ __launch_bounds__(256) void topk_adj(int* __restrict__ aidx,
                                                float* __restrict__ aw)
{
    const int row = blockIdx.x;
    const int tid = threadIdx.x;
    const int lane = tid & 31;
    const int warp = tid >> 5;
    const float* __restrict__ srow = g_sim + (size_t)row * N_NODES;

    float lv[TOPK]; int li[TOPK];
#pragma unroll
    for (int k = 0; k < TOPK; k++) { lv[k] = -FLT_MAX; li[k] = 0x7FFFFFFF; }

#pragma unroll 4
    for (int j = tid; j < N_NODES; j += 256) {
        float v = __ldcs(&srow[j]);
        if (v > lv[TOPK - 1]) {
            lv[TOPK - 1] = v; li[TOPK - 1] = j;
#pragma unroll
            for (int k = TOPK - 1; k > 0; k--) {
                if (lv[k] > lv[k - 1]) {
                    float tv = lv[k]; lv[k] = lv[k - 1]; lv[k - 1] = tv;
                    int   ti = li[k]; li[k] = li[k - 1]; li[k - 1] = ti;
                } else break;
            }
        }
    }

    // ---- stage 1: intra-warp merge (11 rounds of warp argmax; winner advances)
    __shared__ float wvv[8 * TOPK];
    __shared__ int   wvi[8 * TOPK];
    {
        int p = 0;
#pragma unroll
        for (int r = 0; r < TOPK; r++) {
            float cand = (p < TOPK) ? lv[p] : -FLT_MAX;
            int   ci   = (p < TOPK) ? li[p] : 0x7FFFFFFF;
            float mv = cand; int mi = ci;
#pragma unroll
            for (int s = 16; s; s >>= 1) {
                float ov = __shfl_xor_sync(0xffffffffu, mv, s);
                int   oi = __shfl_xor_sync(0xffffffffu, mi, s);
                if (ov > mv || (ov == mv && oi < mi)) { mv = ov; mi = oi; }
            }
            if (lane == r % 32) { /* spread writes */ }
            if (lane == 0) { wvv[warp * TOPK + r] = mv; wvi[warp * TOPK + r] = mi; }
            if (p < TOPK && ci == mi) p++;   // indices unique across the warp
        }
    }
    __syncthreads();

    // ---- stage 2: warp 0 merges 8 sorted lists (lane j < 8 owns list j)
    __shared__ float topv[TOPK];
    __shared__ int   topi[TOPK];
    if (warp == 0) {
        int p = 0;
        float cand = -FLT_MAX; int ci = 0x7FFFFFFF;
        if (lane < 8) { cand = wvv[lane * TOPK]; ci = wvi[lane * TOPK]; }
#pragma unroll
        for (int r = 0; r < TOPK; r++) {
            float mv = cand; int mi = ci;
#pragma unroll
            for (int s = 16; s; s >>= 1) {
                float ov = __shfl_xor_sync(0xffffffffu, mv, s);
                int   oi = __shfl_xor_sync(0xffffffffu, mi, s);
                if (ov > mv || (ov == mv && oi < mi)) { mv = ov; mi = oi; }
            }
            if (lane == 0) { topv[r] = mv; topi[r] = mi; }
            if (lane < 8 && ci == mi) {
                p++;
                if (p < TOPK) { cand = wvv[lane * TOPK + p]; ci = wvi[lane * TOPK + p]; }
                else          { cand = -FLT_MAX; ci = 0x7FFFFFFF; }
            }
        }
    }
    __syncthreads();

    if (tid == 0) {
        float diag = 1.0f;
        float wv[TOPK]; int wi[TOPK]; int cnt = 0;
        for (int k = 1; k < TOPK; k++) {
            if (topi[k] == row) diag += topv[k];
            else { wv[cnt] = topv[k]; wi[cnt] = topi[k]; cnt++; }
        }
        float rs = fabsf(diag);
        for (int k = 0; k < cnt; k++) rs += fabsf(wv[k]);
        rs = fmaxf(rs, 1e-12f);
        const float inv = 1.f / rs;
        aidx[row * TOPK + 0] = row;
        aw[row * TOPK + 0]   = diag * inv;
        for (int k = 0; k < cnt; k++) {
            aidx[row * TOPK + 1 + k] = wi[k];
            aw[row * TOPK + 1 + k]   = wv[k] * inv;
        }
        for (int k = cnt; k < TOPK - 1; k++) {
            aidx[row * TOPK + 1 + k] = row;
            aw[row * TOPK + 1 + k]   = 0.f;
        }
    }
}

// ---------------- sparse adj @ t + bias, leaky(0.25)  (z-batched) ----------------
__global__ void spmm_leaky(const float* __restrict__ t,
                           const float* __restrict__ bias,
                           float* __restrict__ out)
{
    const int z = blockIdx.z;
    const float* tz = t + (size_t)z * NH;
    const float* bz = bias + (size_t)z * HID;
    float* oz = out + (size_t)z * NH;
    const int* ai = g_adj_idx + (size_t)z * N_NODES * TOPK;
    const float* aw = g_adj_w + (size_t)z * N_NODES * TOPK;

    const int row = blockIdx.x;
    const int c = threadIdx.x;
    float acc = bz[c];
#pragma unroll
    for (int k = 0; k < TOPK; k++) {
        int   j = ai[row * TOPK + k];
        float w = aw[row * TOPK + k];
        acc += w * tz[(size_t)j * HID + c];
    }
    oz[(size_t)row * HID + c] = (acc >= 0.f) ? acc : 0.25f * acc;
}

// ---------------- classifier (z-batched): logits = h @ W[256,5] + b --------------
__global__ __launch_bounds__(256) void clf_kernel(const float* __restrict__ h,
                                                  const float* __restrict__ W,
                                                  const float* __restrict__ b)
{
    const int z = blockIdx.z;
    const float* hz = h + (size_t)z * NH;
    const float* Wz = W + (size_t)z * HID * NCLS;
    const float* bz = b + (size_t)z * NCLS;
    float* oz = g_logits + (size_t)z * N_NODES * NCLS;

    __shared__ float Ws[HID * NCLS];
    const int tid = threadIdx.x;
    for (int i = tid; i < HID * NCLS; i += 256) Ws[i] = Wz[i];
    __syncthreads();
    const int warp = tid >> 5, lane = tid & 31;
    const int row = blockIdx.x * 8 + warp;
    float hv[8];
#pragma unroll
    for (int u = 0; u < 8; u++) hv[u] = hz[(size_t)row * HID + lane + 32 * u];
#pragma unroll
    for (int c = 0; c < NCLS; c++) {
        float acc = 0.f;
#pragma unroll
        for (int u = 0; u < 8; u++) acc += hv[u] * Ws[(lane + 32 * u) * NCLS + c];
#pragma unroll
        for (int s = 16; s; s >>= 1) acc += __shfl_down_sync(0xffffffffu, acc, s);
        if (lane == 0) oz[row * NCLS + c] = acc + bz[c];
    }
}

// ---------------- fusion: softmax(attn), sigmoid mix, 5->128->5 MLP ----------------
__global__ __launch_bounds__(256) void fusion_kernel(const float* __restrict__ attn,
                                                     const float* __restrict__ f1W,
                                                     const float* __restrict__ f1b,
                                                     const float* __restrict__ f2W,
                                                     const float* __restrict__ f2b,
                                                     float* __restrict__ out)
{
    __shared__ float s1[NCLS * 128];
    __shared__ float s2[128 * NCLS];
    __shared__ float sb1[128];
    __shared__ float sb2[NCLS];
    const int tid = threadIdx.x;
    for (int i = tid; i < NCLS * 128; i += 256) s1[i] = f1W[i];
    for (int i = tid; i < 128 * NCLS; i += 256) s2[i] = f2W[i];
    if (tid < 128) sb1[tid] = f1b[tid];
    if (tid < NCLS) sb2[tid] = f2b[tid];
    __syncthreads();

    const int row = blockIdx.x * 256 + tid;
    const float a0 = attn[0], a1 = attn[1], a2 = attn[2];
    const float m = fmaxf(a0, fmaxf(a1, a2));
    const float e0 = expf(a0 - m), e1 = expf(a1 - m), e2 = expf(a2 - m);
    const float invs = 1.f / (e0 + e1 + e2);
    const float w0 = e0 * invs, w1 = e1 * invs, w2 = e2 * invs;

    float fused[NCLS];
#pragma unroll
    for (int c = 0; c < NCLS; c++) {
        float l0 = g_logits[0 * N_NODES * NCLS + row * NCLS + c];
        float l1 = g_logits[1 * N_NODES * NCLS + row * NCLS + c];
        float l2 = g_logits[2 * N_NODES * NCLS + row * NCLS + c];
        fused[c] = w0 / (1.f + expf(-l0)) + w1 / (1.f + expf(-l1)) + w2 / (1.f + expf(-l2));
    }
    float o[NCLS];
#pragma unroll
    for (int c = 0; c < NCLS; c++) o[c] = sb2[c];
    for (int j = 0; j < 128; j++) {
        float t = sb1[j];
#pragma unroll
        for (int c = 0; c < NCLS; c++) t += fused[c] * s1[c * 128 + j];
        t = (t >= 0.f) ? t : 0.25f * t;
#pragma unroll
        for (int c = 0; c < NCLS; c++) o[c] += t * s2[j * NCLS + c];
    }
#pragma unroll
    for (int c = 0; c < NCLS; c++) out[(size_t)row * NCLS + c] = o[c];
}

// ---------------- host launcher ----------------
extern "C" void kernel_launch(void* const* d_in, const int* in_sizes, int n_in,
                              void* d_out, int out_size)
{
    (void)n_in; (void)out_size;
    const float* x[3]    = {(const float*)d_in[0], (const float*)d_in[1], (const float*)d_in[2]};
    const float* encW[3] = {(const float*)d_in[3], (const float*)d_in[4], (const float*)d_in[5]};
    const float* enc_b = (const float*)d_in[6];
    const float* bn_g  = (const float*)d_in[7];
    const float* bn_b  = (const float*)d_in[8];
    const float* gc1W  = (const float*)d_in[9];
    const float* gc1b  = (const float*)d_in[10];
    const float* gc2W  = (const float*)d_in[11];
    const float* gc2b  = (const float*)d_in[12];
    const float* clfW  = (const float*)d_in[13];
    const float* clfb  = (const float*)d_in[14];
    const float* attn  = (const float*)d_in[15];
    const float* f1W   = (const float*)d_in[16];
    const float* f1b   = (const float*)d_in[17];
    const float* f2W   = (const float*)d_in[18];
    const float* f2b   = (const float*)d_in[19];

    float *p_sim, *p_t, *p_feat, *p_fn, *p_h;
    int   *p_aidx; float *p_aw;
    cudaGetSymbolAddress((void**)&p_sim,  g_sim);
    cudaGetSymbolAddress((void**)&p_t,    g_t);
    cudaGetSymbolAddress((void**)&p_feat, g_feat);
    cudaGetSymbolAddress((void**)&p_fn,   g_fn);
    cudaGetSymbolAddress((void**)&p_h,    g_h);
    cudaGetSymbolAddress((void**)&p_aidx, g_adj_idx);
    cudaGetSymbolAddress((void**)&p_aw,   g_adj_w);

    const int NTILE = N_NODES / 128;
    const int NSYMM = NTILE * (NTILE + 1) / 2;   // 2080

    const int K0 = in_sizes[0] / N_NODES;
    const int K1 = in_sizes[1] / N_NODES;
    const int K2 = in_sizes[2] / N_NODES;

    // ---- encoders: one z=3 batched launch (per-z A/B/K) ----
    gemm_bf16x3<false, true, false, false, true><<<dim3(HID / 128, N_NODES / 128, 3), 256>>>(
        x[0], encW[0], enc_b, p_t, N_NODES, HID, K0,
        0, 0, HID, NH,
        x[1], encW[1], K1, x[2], encW[2], K2);

    // ---- batchnorm + rownorm (batched over z) ----
    bn_colpart<<<dim3(64, 1, 3), 256>>>();
    bn_colfinal<<<dim3(1, 1, 3), 256>>>(bn_g, bn_b);
    bn_apply_rownorm<<<dim3(N_NODES / 8, 1, 3), 256>>>();

    // ---- per modality: sim (symmetric) + topk (g_sim reused) ----
    for (int i = 0; i < 3; i++) {
        gemm_bf16x3<true, false, true, true, false><<<dim3(NSYMM, 1, 1), 256>>>(
            p_fn + (size_t)i * NH, p_fn + (size_t)i * NH, nullptr,
            p_sim, N_NODES, N_NODES, HID, 0, 0, 0, 0,
            nullptr, nullptr, 0, nullptr, nullptr, 0);
        topk_adj<<<N_NODES, 256>>>(p_aidx + (size_t)i * N_NODES * TOPK,
                                   p_aw   + (size_t)i * N_NODES * TOPK);
    }

    // ---- GCN layers (batched z=3) ----
    {
        dim3 grid(HID / 128, N_NODES / 128, 3);
        gemm_bf16x3<false, false, true, false, false><<<grid, 256>>>(p_feat, gc1W, nullptr, p_t,
            N_NODES, HID, HID, NH, HID * HID, 0, NH,
            nullptr, nullptr, 0, nullptr, nullptr, 0);
        spmm_leaky<<<dim3(N_NODES, 1, 3), HID>>>(p_t, gc1b, p_h);
        gemm_bf16x3<false, false, true, false, false><<<grid, 256>>>(p_h, gc2W, nullptr, p_t,
            N_NODES, HID, HID, NH, HID * HID, 0, NH,
            nullptr, nullptr, 0, nullptr, nullptr, 0);
        spmm_leaky<<<dim3(N_NODES, 1, 3), HID>>>(p_t, gc2b, p_h);
    }

    // ---- classifier (batched) + fusion ----
    clf_kernel<<<dim3(N_NODES / 8, 1, 3), 256>>>(p_h, clfW, clfb);
    fusion_kernel<<<N_NODES / 256, 256>>>(attn, f1W, f1b, f2W, f2b, (float*)d_out);
}

// round 9
// speedup vs baseline: 1.0341x; 1.0341x over previous
#include <cuda_runtime.h>
#include <math.h>
#include <float.h>
#include <stdint.h>

#define N_NODES 8192
#define HID 256
#define NCLS 5
#define TOPK 11   // K+1
#define SSTR 20   // smem row stride in uint32 (bf16-pair) units; 16 pairs + 4 pad
#define NH (N_NODES * HID)

// ---------------- scratch (static device globals; no allocation) ----------------
__device__ float g_sim[(size_t)N_NODES * N_NODES];   // 256 MB (reused per modality)
__device__ float g_t[3 * NH];
__device__ float g_feat[3 * NH];
__device__ float g_fn[3 * NH];
__device__ float g_h[3 * NH];
__device__ float g_part[3 * 2 * 64 * HID];
__device__ float g_bna[3 * HID];
__device__ float g_bnc[3 * HID];
__device__ int   g_adj_idx[3 * N_NODES * TOPK];
__device__ float g_adj_w[3 * N_NODES * TOPK];
__device__ float g_logits[3 * N_NODES * NCLS];

// pack two floats to bf16x2 (low = x, high = y), round-to-nearest
__device__ __forceinline__ uint32_t pack_bf16(float x, float y)
{
    uint32_t r;
    asm("cvt.rn.bf16x2.f32 %0, %1, %2;" : "=r"(r) : "f"(y), "f"(x));
    return r;
}
__device__ __forceinline__ float bf16lo_f(uint32_t p) { return __uint_as_float(p << 16); }
__device__ __forceinline__ float bf16hi_f(uint32_t p) { return __uint_as_float(p & 0xFFFF0000u); }

__device__ __forceinline__ void split4(float4 v, uint32_t& h0, uint32_t& h1,
                                       uint32_t& l0, uint32_t& l1)
{
    h0 = pack_bf16(v.x, v.y);
    h1 = pack_bf16(v.z, v.w);
    l0 = pack_bf16(v.x - bf16lo_f(h0), v.y - bf16hi_f(h0));
    l1 = pack_bf16(v.z - bf16lo_f(h1), v.w - bf16hi_f(h1));
}

#define MMA_BF16(C, A, B) \
    asm volatile( \
        "mma.sync.aligned.m16n8k16.row.col.f32.bf16.bf16.f32 " \
        "{%0,%1,%2,%3}, {%4,%5,%6,%7}, {%8,%9}, {%0,%1,%2,%3};\n" \
        : "+f"((C)[0]), "+f"((C)[1]), "+f"((C)[2]), "+f"((C)[3]) \
        : "r"((A)[0]), "r"((A)[1]), "r"((A)[2]), "r"((A)[3]), \
          "r"((B)[0]), "r"((B)[1]))

#define LDSM_X4(r0, r1, r2, r3, addr) \
    asm volatile("ldmatrix.sync.aligned.m8n8.x4.shared.b16 {%0,%1,%2,%3}, [%4];" \
        : "=r"(r0), "=r"(r1), "=r"(r2), "=r"(r3) : "r"(addr))

__device__ __forceinline__ uint32_t smem_u32(const void* p)
{
    return (uint32_t)__cvta_generic_to_shared(p);
}

// ---------------- bf16x3 split-precision tensor-core GEMM ------------------------
// C[M,N] = A[M,K] * op(B) (+bias,+relu).  Dekker split: Ahi*Bhi + Ahi*Blo + Alo*Bhi.
// TRANSB=true : B is [N,K] row-major (C = A * B^T); false: B is [K,N].
// VEC4: COMPILE-TIME float4 global loads for A (and B when TRANSB); K%4==0 required.
// SYMM: A==B, C symmetric, linear grid over lower-tri tiles, off-diag mirrored.
// Batched over blockIdx.z via zs* strides. ldmatrix fragments + register prefetch.
template<bool TRANSB, bool BIAS_RELU, bool VEC4, bool SYMM>
__global__ __launch_bounds__(256) void gemm_bf16x3(const float* __restrict__ A,
                                                   const float* __restrict__ B,
                                                   const float* __restrict__ bias,
                                                   float* __restrict__ C,
                                                   int M, int N, int K,
                                                   int zsA, int zsB, int zsBias, int zsC)
{
    __shared__ uint32_t sAhi[128 * SSTR];
    __shared__ uint32_t sAlo[128 * SSTR];
    __shared__ uint32_t sBhi[128 * SSTR];
    __shared__ uint32_t sBlo[128 * SSTR];

    A += (size_t)blockIdx.z * zsA;
    B += (size_t)blockIdx.z * zsB;
    if (BIAS_RELU) bias += (size_t)blockIdx.z * zsBias;
    C += (size_t)blockIdx.z * zsC;

    const int tid  = threadIdx.x;
    const int lane = tid & 31;
    const int warp = tid >> 5;
    const int gid  = lane >> 2;
    const int tig  = lane & 3;
    const int wm   = warp >> 2;     // 0..1 -> m offset wm*64
    const int wn   = warp & 3;      // 0..3 -> n offset wn*32

    int mo, no;
    bool mirror = false;
    if (SYMM) {
        int t = blockIdx.x;
        int bi = (int)((sqrtf(8.f * (float)t + 1.f) - 1.f) * 0.5f);
        while ((bi + 1) * (bi + 2) / 2 <= t) bi++;
        while (bi * (bi + 1) / 2 > t) bi--;
        int bj = t - bi * (bi + 1) / 2;
        mo = bi * 128; no = bj * 128;
        mirror = (bi != bj);
    } else {
        mo = blockIdx.y * 128;
        no = blockIdx.x * 128;
    }

    float acc[4][4][4];
#pragma unroll
    for (int i = 0; i < 4; i++)
#pragma unroll
        for (int j = 0; j < 4; j++)
#pragma unroll
            for (int q = 0; q < 4; q++) acc[i][j][q] = 0.f;

    // ldmatrix lane address components (bytes)
    const uint32_t aoff = (uint32_t)((wm * 64 + (lane & 7) + ((lane >> 3) & 1) * 8) * (SSTR * 4)
                                     + ((lane >> 4) & 1) * 16);
    const uint32_t boff = (uint32_t)((wn * 32 + (lane & 7) + ((lane >> 4) & 1) * 8) * (SSTR * 4)
                                     + ((lane >> 3) & 1) * 16);
    const uint32_t baseAhi = smem_u32(sAhi), baseAlo = smem_u32(sAlo);
    const uint32_t baseBhi = smem_u32(sBhi), baseBlo = smem_u32(sBlo);

    auto loadA = [&](int ko, int u) -> float4 {
        int f = u * 256 + tid;
        int r = f >> 3, kq = f & 7;
        int gk = ko + kq * 4;
        float4 v;
        if (VEC4 && gk + 3 < K) {
            v = *reinterpret_cast<const float4*>(&A[(size_t)(mo + r) * K + gk]);
        } else {
            const float* p = &A[(size_t)(mo + r) * K];
            v.x = (gk + 0 < K) ? p[gk + 0] : 0.f;
            v.y = (gk + 1 < K) ? p[gk + 1] : 0.f;
            v.z = (gk + 2 < K) ? p[gk + 2] : 0.f;
            v.w = (gk + 3 < K) ? p[gk + 3] : 0.f;
        }
        return v;
    };
    auto loadB = [&](int ko, int u) -> float4 {
        float4 v;
        if (TRANSB) {
            int f = u * 256 + tid;
            int r = f >> 3, kq = f & 7;
            int gk = ko + kq * 4;
            if (VEC4 && gk + 3 < K) {
                v = *reinterpret_cast<const float4*>(&B[(size_t)(no + r) * K + gk]);
            } else {
                const float* p = &B[(size_t)(no + r) * K];
                v.x = (gk + 0 < K) ? p[gk + 0] : 0.f;
                v.y = (gk + 1 < K) ? p[gk + 1] : 0.f;
                v.z = (gk + 2 < K) ? p[gk + 2] : 0.f;
                v.w = (gk + 3 < K) ? p[gk + 3] : 0.f;
            }
        } else {
            int f = u * 256 + tid;
            int n = f & 127;
            int kq = f >> 7;
            int gk = ko + kq * 4;
            v.x = (gk + 0 < K) ? B[(size_t)(gk + 0) * N + no + n] : 0.f;
            v.y = (gk + 1 < K) ? B[(size_t)(gk + 1) * N + no + n] : 0.f;
            v.z = (gk + 2 < K) ? B[(size_t)(gk + 2) * N + no + n] : 0.f;
            v.w = (gk + 3 < K) ? B[(size_t)(gk + 3) * N + no + n] : 0.f;
        }
        return v;
    };

    float4 va[4], vb[4];
#pragma unroll
    for (int u = 0; u < 4; u++) { va[u] = loadA(0, u); vb[u] = loadB(0, u); }

    for (int ko = 0; ko < K; ko += 32) {
#pragma unroll
        for (int u = 0; u < 4; u++) {
            int f = u * 256 + tid;
            uint32_t h0, h1, l0, l1;
            {   // A: [row][pair]
                int r = f >> 3, kq = f & 7;
                split4(va[u], h0, h1, l0, l1);
                int w = r * SSTR + kq * 2;
                sAhi[w] = h0; sAhi[w + 1] = h1;
                sAlo[w] = l0; sAlo[w + 1] = l1;
            }
            {   // B: [n][pair]
                int r, kq;
                if (TRANSB) { r = f >> 3; kq = f & 7; }
                else        { r = f & 127; kq = f >> 7; }
                split4(vb[u], h0, h1, l0, l1);
                int w = r * SSTR + kq * 2;
                sBhi[w] = h0; sBhi[w + 1] = h1;
                sBlo[w] = l0; sBlo[w + 1] = l1;
            }
        }
        __syncthreads();

        const int kn = ko + 32;
        if (kn < K) {
#pragma unroll
            for (int u = 0; u < 4; u++) { va[u] = loadA(kn, u); vb[u] = loadB(kn, u); }
        }

#pragma unroll
        for (int ks = 0; ks < 2; ks++) {
            const uint32_t kb = (uint32_t)(ks * 32);
            uint32_t bhi[4][2], blo[4][2];
#pragma unroll
            for (int p = 0; p < 2; p++) {
                LDSM_X4(bhi[2 * p][0], bhi[2 * p][1], bhi[2 * p + 1][0], bhi[2 * p + 1][1],
                        baseBhi + boff + (uint32_t)(p * 16 * SSTR * 4) + kb);
                LDSM_X4(blo[2 * p][0], blo[2 * p][1], blo[2 * p + 1][0], blo[2 * p + 1][1],
                        baseBlo + boff + (uint32_t)(p * 16 * SSTR * 4) + kb);
            }
#pragma unroll
            for (int i = 0; i < 4; i++) {
                uint32_t ahi[4], alo[4];
                LDSM_X4(ahi[0], ahi[1], ahi[2], ahi[3],
                        baseAhi + aoff + (uint32_t)(i * 16 * SSTR * 4) + kb);
                LDSM_X4(alo[0], alo[1], alo[2], alo[3],
                        baseAlo + aoff + (uint32_t)(i * 16 * SSTR * 4) + kb);
#pragma unroll
                for (int j = 0; j < 4; j++) {
                    MMA_BF16(acc[i][j], ahi, bhi[j]);
                    MMA_BF16(acc[i][j], ahi, blo[j]);
                    MMA_BF16(acc[i][j], alo, bhi[j]);
                }
            }
        }
        __syncthreads();
    }

    // ---- epilogue
#pragma unroll
    for (int i = 0; i < 4; i++) {
        const int r0 = mo + wm * 64 + i * 16 + gid;
#pragma unroll
        for (int j = 0; j < 4; j++) {
            const int c = no + wn * 32 + j * 8 + tig * 2;
            float v0 = acc[i][j][0], v1 = acc[i][j][1];
            float v2 = acc[i][j][2], v3 = acc[i][j][3];
            if (BIAS_RELU) {
                const float b0 = bias[c], b1 = bias[c + 1];
                v0 = fmaxf(v0 + b0, 0.f); v1 = fmaxf(v1 + b1, 0.f);
                v2 = fmaxf(v2 + b0, 0.f); v3 = fmaxf(v3 + b1, 0.f);
            }
            *reinterpret_cast<float2*>(&C[(size_t)r0 * N + c])       = make_float2(v0, v1);
            *reinterpret_cast<float2*>(&C[(size_t)(r0 + 8) * N + c]) = make_float2(v2, v3);
            if (SYMM && mirror) {
                C[(size_t)c * N + r0]           = v0;
                C[(size_t)(c + 1) * N + r0]     = v1;
                C[(size_t)c * N + r0 + 8]       = v2;
                C[(size_t)(c + 1) * N + r0 + 8] = v3;
            }
        }
    }
}

// ---------------- BatchNorm stats (two stage, deterministic, z-batched) ----------
__global__ void bn_colpart(void)
{
    const int z = blockIdx.z;
    const float* t = g_t + (size_t)z * NH;
    float* part = g_part + (size_t)z * 2 * 64 * HID;
    const int c = threadIdx.x;
    const int r0 = blockIdx.x * 128;
    float s = 0.f, s2 = 0.f;
    for (int r = r0; r < r0 + 128; r++) {
        float v = t[(size_t)r * HID + c];
        s += v; s2 += v * v;
    }
    part[blockIdx.x * HID + c] = s;
    part[64 * HID + blockIdx.x * HID + c] = s2;
}

__global__ void bn_colfinal(const float* __restrict__ gam, const float* __restrict__ bet)
{
    const int z = blockIdx.z;
    const float* part = g_part + (size_t)z * 2 * 64 * HID;
    const int c = threadIdx.x;
    float s = 0.f, s2 = 0.f;
    for (int b = 0; b < 64; b++) {
        s  += part[b * HID + c];
        s2 += part[64 * HID + b * HID + c];
    }
    const float mu = s * (1.f / N_NODES);
    float var = s2 * (1.f / N_NODES) - mu * mu;
    const float a = gam[z * HID + c] * rsqrtf(var + 1e-5f);
    g_bna[z * HID + c] = a;
    g_bnc[z * HID + c] = bet[z * HID + c] - mu * a;
}

__global__ __launch_bounds__(256) void bn_apply_rownorm(void)
{
    const int z = blockIdx.z;
    const float* t = g_t + (size_t)z * NH;
    float* feat = g_feat + (size_t)z * NH;
    float* fn   = g_fn   + (size_t)z * NH;
    const int tid = threadIdx.x;
    const int warp = tid >> 5, lane = tid & 31;
    const int row = blockIdx.x * 8 + warp;
    float v[8];
    float sq = 0.f;
#pragma unroll
    for (int u = 0; u < 8; u++) {
        int c = lane + 32 * u;
        float x = g_bna[z * HID + c] * t[(size_t)row * HID + c] + g_bnc[z * HID + c];
        v[u] = x; sq += x * x;
    }
#pragma unroll
    for (int s = 16; s; s >>= 1) sq += __shfl_xor_sync(0xffffffffu, sq, s);
    const float norm = sqrtf(sq);
    const float inv = 1.f / fmaxf(norm, 1e-12f);
#pragma unroll
    for (int u = 0; u < 8; u++) {
        int c = lane + 32 * u;
        feat[(size_t)row * HID + c] = v[u];
        fn[(size_t)row * HID + c]   = v[u] * inv;
    }
}

// ---------------- top-(K+1) per row + sparse adjacency build ----------------------
// Hierarchical shuffle merge: per-thread sorted lists -> intra-warp argmax rounds
// (no barriers) -> one __syncthreads -> warp 0 merges the 8 warp lists.
// Tie-break everywhere: higher value wins; equal value -> lower index wins.
__global__ __launch_bounds__(256) void topk_adj(int* __restrict__ aidx,
                                                float* __restrict__ aw)
{
    const int row = blockIdx.x;
    const int tid = threadIdx.x;
    const int lane = tid & 31;
    const int warp = tid >> 5;
    const float* __restrict__ srow = g_sim + (size_t)row * N_NODES;

    float lv[TOPK]; int li[TOPK];
#pragma unroll
    for (int k = 0; k < TOPK; k++) { lv[k] = -FLT_MAX; li[k] = 0x7FFFFFFF; }

    for (int j = tid; j < N_NODES; j += 256) {
        float v = srow[j];
        if (v > lv[TOPK - 1]) {
            lv[TOPK - 1] = v; li[TOPK - 1] = j;
#pragma unroll
            for (int k = TOPK - 1; k > 0; k--) {
                if (lv[k] > lv[k - 1]) {
                    float tv = lv[k]; lv[k] = lv[k - 1]; lv[k - 1] = tv;
                    int   ti = li[k]; li[k] = li[k - 1]; li[k - 1] = ti;
                } else break;
            }
        }
    }

    // ---- stage 1: intra-warp merge (11 rounds of warp argmax; owner advances)
    __shared__ float wvv[8 * TOPK];
    __shared__ int   wvi[8 * TOPK];
    {
        int p = 0;
#pragma unroll
        for (int r = 0; r < TOPK; r++) {
            float cand = (p < TOPK) ? lv[p] : -FLT_MAX;
            int   ci   = (p < TOPK) ? li[p] : 0x7FFFFFFF;
            float mv = cand; int mi = ci;
#pragma unroll
            for (int s = 16; s; s >>= 1) {
                float ov = __shfl_xor_sync(0xffffffffu, mv, s);
                int   oi = __shfl_xor_sync(0xffffffffu, mi, s);
                if (ov > mv || (ov == mv && oi < mi)) { mv = ov; mi = oi; }
            }
            if (lane == 0) { wvv[warp * TOPK + r] = mv; wvi[warp * TOPK + r] = mi; }
            if (p < TOPK && ci == mi) p++;   // indices unique across the warp
        }
    }
    __syncthreads();

    // ---- stage 2: warp 0 merges 8 sorted lists (lane j < 8 owns list j)
    __shared__ float topv[TOPK];
    __shared__ int   topi[TOPK];
    if (warp == 0) {
        int p = 0;
        float cand = -FLT_MAX; int ci = 0x7FFFFFFF;
        if (lane < 8) { cand = wvv[lane * TOPK]; ci = wvi[lane * TOPK]; }
#pragma unroll
        for (int r = 0; r < TOPK; r++) {
            float mv = cand; int mi = ci;
#pragma unroll
            for (int s = 16; s; s >>= 1) {
                float ov = __shfl_xor_sync(0xffffffffu, mv, s);
                int   oi = __shfl_xor_sync(0xffffffffu, mi, s);
                if (ov > mv || (ov == mv && oi < mi)) { mv = ov; mi = oi; }
            }
            if (lane == 0) { topv[r] = mv; topi[r] = mi; }
            if (lane < 8 && ci == mi) {
                p++;
                if (p < TOPK) { cand = wvv[lane * TOPK + p]; ci = wvi[lane * TOPK + p]; }
                else          { cand = -FLT_MAX; ci = 0x7FFFFFFF; }
            }
        }

        if (lane == 0) {
            float diag = 1.0f;
            float wv[TOPK]; int wi[TOPK]; int cnt = 0;
            for (int k = 1; k < TOPK; k++) {
                if (topi[k] == row) diag += topv[k];
                else { wv[cnt] = topv[k]; wi[cnt] = topi[k]; cnt++; }
            }
            float rs = fabsf(diag);
            for (int k = 0; k < cnt; k++) rs += fabsf(wv[k]);
            rs = fmaxf(rs, 1e-12f);
            const float inv = 1.f / rs;
            aidx[row * TOPK + 0] = row;
            aw[row * TOPK + 0]   = diag * inv;
            for (int k = 0; k < cnt; k++) {
                aidx[row * TOPK + 1 + k] = wi[k];
                aw[row * TOPK + 1 + k]   = wv[k] * inv;
            }
            for (int k = cnt; k < TOPK - 1; k++) {
                aidx[row * TOPK + 1 + k] = row;
                aw[row * TOPK + 1 + k]   = 0.f;
            }
        }
    }
}

// ---------------- sparse adj @ t + bias, leaky(0.25)  (z-batched) ----------------
__global__ void spmm_leaky(const float* __restrict__ t,
                           const float* __restrict__ bias,
                           float* __restrict__ out)
{
    const int z = blockIdx.z;
    const float* tz = t + (size_t)z * NH;
    const float* bz = bias + (size_t)z * HID;
    float* oz = out + (size_t)z * NH;
    const int* ai = g_adj_idx + (size_t)z * N_NODES * TOPK;
    const float* aw = g_adj_w + (size_t)z * N_NODES * TOPK;

    const int row = blockIdx.x;
    const int c = threadIdx.x;
    float acc = bz[c];
#pragma unroll
    for (int k = 0; k < TOPK; k++) {
        int   j = ai[row * TOPK + k];
        float w = aw[row * TOPK + k];
        acc += w * tz[(size_t)j * HID + c];
    }
    oz[(size_t)row * HID + c] = (acc >= 0.f) ? acc : 0.25f * acc;
}

// ---------------- classifier (z-batched): logits = h @ W[256,5] + b --------------
__global__ __launch_bounds__(256) void clf_kernel(const float* __restrict__ h,
                                                  const float* __restrict__ W,
                                                  const float* __restrict__ b)
{
    const int z = blockIdx.z;
    const float* hz = h + (size_t)z * NH;
    const float* Wz = W + (size_t)z * HID * NCLS;
    const float* bz = b + (size_t)z * NCLS;
    float* oz = g_logits + (size_t)z * N_NODES * NCLS;

    __shared__ float Ws[HID * NCLS];
    const int tid = threadIdx.x;
    for (int i = tid; i < HID * NCLS; i += 256) Ws[i] = Wz[i];
    __syncthreads();
    const int warp = tid >> 5, lane = tid & 31;
    const int row = blockIdx.x * 8 + warp;
    float hv[8];
#pragma unroll
    for (int u = 0; u < 8; u++) hv[u] = hz[(size_t)row * HID + lane + 32 * u];
#pragma unroll
    for (int c = 0; c < NCLS; c++) {
        float acc = 0.f;
#pragma unroll
        for (int u = 0; u < 8; u++) acc += hv[u] * Ws[(lane + 32 * u) * NCLS + c];
#pragma unroll
        for (int s = 16; s; s >>= 1) acc += __shfl_down_sync(0xffffffffu, acc, s);
        if (lane == 0) oz[row * NCLS + c] = acc + bz[c];
    }
}

// ---------------- fusion: softmax(attn), sigmoid mix, 5->128->5 MLP ----------------
__global__ __launch_bounds__(256) void fusion_kernel(const float* __restrict__ attn,
                                                     const float* __restrict__ f1W,
                                                     const float* __restrict__ f1b,
                                                     const float* __restrict__ f2W,
                                                     const float* __restrict__ f2b,
                                                     float* __restrict__ out)
{
    __shared__ float s1[NCLS * 128];
    __shared__ float s2[128 * NCLS];
    __shared__ float sb1[128];
    __shared__ float sb2[NCLS];
    const int tid = threadIdx.x;
    for (int i = tid; i < NCLS * 128; i += 256) s1[i] = f1W[i];
    for (int i = tid; i < 128 * NCLS; i += 256) s2[i] = f2W[i];
    if (tid < 128) sb1[tid] = f1b[tid];
    if (tid < NCLS) sb2[tid] = f2b[tid];
    __syncthreads();

    const int row = blockIdx.x * 256 + tid;
    const float a0 = attn[0], a1 = attn[1], a2 = attn[2];
    const float m = fmaxf(a0, fmaxf(a1, a2));
    const float e0 = expf(a0 - m), e1 = expf(a1 - m), e2 = expf(a2 - m);
    const float invs = 1.f / (e0 + e1 + e2);
    const float w0 = e0 * invs, w1 = e1 * invs, w2 = e2 * invs;

    float fused[NCLS];
#pragma unroll
    for (int c = 0; c < NCLS; c++) {
        float l0 = g_logits[0 * N_NODES * NCLS + row * NCLS + c];
        float l1 = g_logits[1 * N_NODES * NCLS + row * NCLS + c];
        float l2 = g_logits[2 * N_NODES * NCLS + row * NCLS + c];
        fused[c] = w0 / (1.f + expf(-l0)) + w1 / (1.f + expf(-l1)) + w2 / (1.f + expf(-l2));
    }
    float o[NCLS];
#pragma unroll
    for (int c = 0; c < NCLS; c++) o[c] = sb2[c];
    for (int j = 0; j < 128; j++) {
        float t = sb1[j];
#pragma unroll
        for (int c = 0; c < NCLS; c++) t += fused[c] * s1[c * 128 + j];
        t = (t >= 0.f) ? t : 0.25f * t;
#pragma unroll
        for (int c = 0; c < NCLS; c++) o[c] += t * s2[j * NCLS + c];
    }
#pragma unroll
    for (int c = 0; c < NCLS; c++) out[(size_t)row * NCLS + c] = o[c];
}

// ---------------- host launcher ----------------
extern "C" void kernel_launch(void* const* d_in, const int* in_sizes, int n_in,
                              void* d_out, int out_size)
{
    (void)n_in; (void)out_size;
    const float* x[3]    = {(const float*)d_in[0], (const float*)d_in[1], (const float*)d_in[2]};
    const float* encW[3] = {(const float*)d_in[3], (const float*)d_in[4], (const float*)d_in[5]};
    const float* enc_b = (const float*)d_in[6];
    const float* bn_g  = (const float*)d_in[7];
    const float* bn_b  = (const float*)d_in[8];
    const float* gc1W  = (const float*)d_in[9];
    const float* gc1b  = (const float*)d_in[10];
    const float* gc2W  = (const float*)d_in[11];
    const float* gc2b  = (const float*)d_in[12];
    const float* clfW  = (const float*)d_in[13];
    const float* clfb  = (const float*)d_in[14];
    const float* attn  = (const float*)d_in[15];
    const float* f1W   = (const float*)d_in[16];
    const float* f1b   = (const float*)d_in[17];
    const float* f2W   = (const float*)d_in[18];
    const float* f2b   = (const float*)d_in[19];

    float *p_sim, *p_t, *p_feat, *p_fn, *p_h;
    int   *p_aidx; float *p_aw;
    cudaGetSymbolAddress((void**)&p_sim,  g_sim);
    cudaGetSymbolAddress((void**)&p_t,    g_t);
    cudaGetSymbolAddress((void**)&p_feat, g_feat);
    cudaGetSymbolAddress((void**)&p_fn,   g_fn);
    cudaGetSymbolAddress((void**)&p_h,    g_h);
    cudaGetSymbolAddress((void**)&p_aidx, g_adj_idx);
    cudaGetSymbolAddress((void**)&p_aw,   g_adj_w);

    const int NTILE = N_NODES / 128;
    const int NSYMM = NTILE * (NTILE + 1) / 2;   // 2080

    // ---- encoders (separate launches, compile-time VEC4 selection) ----
    for (int i = 0; i < 3; i++) {
        const int Kenc = in_sizes[i] / N_NODES;
        dim3 grid(HID / 128, N_NODES / 128, 1);
        if ((Kenc & 3) == 0)
            gemm_bf16x3<false, true, true, false><<<grid, 256>>>(x[i], encW[i], enc_b + i * HID,
                p_t + (size_t)i * NH, N_NODES, HID, Kenc, 0, 0, 0, 0);
        else
            gemm_bf16x3<false, true, false, false><<<grid, 256>>>(x[i], encW[i], enc_b + i * HID,
                p_t + (size_t)i * NH, N_NODES, HID, Kenc, 0, 0, 0, 0);
    }

    // ---- batchnorm + rownorm (batched over z) ----
    bn_colpart<<<dim3(64, 1, 3), 256>>>();
    bn_colfinal<<<dim3(1, 1, 3), 256>>>(bn_g, bn_b);
    bn_apply_rownorm<<<dim3(N_NODES / 8, 1, 3), 256>>>();

    // ---- per modality: sim (symmetric) + topk (g_sim reused) ----
    for (int i = 0; i < 3; i++) {
        gemm_bf16x3<true, false, true, true><<<dim3(NSYMM, 1, 1), 256>>>(
            p_fn + (size_t)i * NH, p_fn + (size_t)i * NH, nullptr,
            p_sim, N_NODES, N_NODES, HID, 0, 0, 0, 0);
        topk_adj<<<N_NODES, 256>>>(p_aidx + (size_t)i * N_NODES * TOPK,
                                   p_aw   + (size_t)i * N_NODES * TOPK);
    }

    // ---- GCN layers (batched z=3) ----
    {
        dim3 grid(HID / 128, N_NODES / 128, 3);
        gemm_bf16x3<false, false, true, false><<<grid, 256>>>(p_feat, gc1W, nullptr, p_t,
            N_NODES, HID, HID, NH, HID * HID, 0, NH);
        spmm_leaky<<<dim3(N_NODES, 1, 3), HID>>>(p_t, gc1b, p_h);
        gemm_bf16x3<false, false, true, false><<<grid, 256>>>(p_h, gc2W, nullptr, p_t,
            N_NODES, HID, HID, NH, HID * HID, 0, NH);
        spmm_leaky<<<dim3(N_NODES, 1, 3), HID>>>(p_t, gc2b, p_h);
    }

    // ---- classifier (batched) + fusion ----
    clf_kernel<<<dim3(N_NODES / 8, 1, 3), 256>>>(p_h, clfW, clfb);
    fusion_kernel<<<N_NODES / 256, 256>>>(attn, f1W, f1b, f2W, f2b, (float*)d_out);
}

// round 10
// speedup vs baseline: 1.6024x; 1.5496x over previous
#include <cuda_runtime.h>
#include <math.h>
#include <float.h>
#include <stdint.h>

#define N_NODES 8192
#define HID 256
#define NCLS 5
#define TOPK 11   // K+1
#define SSTR 20   // smem row stride in uint32 (bf16-pair) units; 16 pairs + 4 pad
#define NH (N_NODES * HID)

// ---------------- scratch (static device globals; no allocation) ----------------
__device__ float g_sim[(size_t)N_NODES * N_NODES];   // 256 MB (reused per modality)
__device__ float g_t[3 * NH];
__device__ float g_feat[3 * NH];
__device__ float g_fn[3 * NH];
__device__ float g_h[3 * NH];
__device__ float g_part[3 * 2 * 64 * HID];
__device__ float g_bna[3 * HID];
__device__ float g_bnc[3 * HID];
__device__ int   g_adj_idx[3 * N_NODES * TOPK];
__device__ float g_adj_w[3 * N_NODES * TOPK];
__device__ float g_logits[3 * N_NODES * NCLS];

// pack two floats to bf16x2 (low = x, high = y), round-to-nearest
__device__ __forceinline__ uint32_t pack_bf16(float x, float y)
{
    uint32_t r;
    asm("cvt.rn.bf16x2.f32 %0, %1, %2;" : "=r"(r) : "f"(y), "f"(x));
    return r;
}
__device__ __forceinline__ float bf16lo_f(uint32_t p) { return __uint_as_float(p << 16); }
__device__ __forceinline__ float bf16hi_f(uint32_t p) { return __uint_as_float(p & 0xFFFF0000u); }

__device__ __forceinline__ void split4(float4 v, uint32_t& h0, uint32_t& h1,
                                       uint32_t& l0, uint32_t& l1)
{
    h0 = pack_bf16(v.x, v.y);
    h1 = pack_bf16(v.z, v.w);
    l0 = pack_bf16(v.x - bf16lo_f(h0), v.y - bf16hi_f(h0));
    l1 = pack_bf16(v.z - bf16lo_f(h1), v.w - bf16hi_f(h1));
}

#define MMA_BF16(C, A, B) \
    asm volatile( \
        "mma.sync.aligned.m16n8k16.row.col.f32.bf16.bf16.f32 " \
        "{%0,%1,%2,%3}, {%4,%5,%6,%7}, {%8,%9}, {%0,%1,%2,%3};\n" \
        : "+f"((C)[0]), "+f"((C)[1]), "+f"((C)[2]), "+f"((C)[3]) \
        : "r"((A)[0]), "r"((A)[1]), "r"((A)[2]), "r"((A)[3]), \
          "r"((B)[0]), "r"((B)[1]))

#define LDSM_X4(r0, r1, r2, r3, addr) \
    asm volatile("ldmatrix.sync.aligned.m8n8.x4.shared.b16 {%0,%1,%2,%3}, [%4];" \
        : "=r"(r0), "=r"(r1), "=r"(r2), "=r"(r3) : "r"(addr))

__device__ __forceinline__ uint32_t smem_u32(const void* p)
{
    return (uint32_t)__cvta_generic_to_shared(p);
}

// ---------------- bf16x3 split-precision tensor-core GEMM ------------------------
// C[M,N] = A[M,K] * op(B) (+bias,+relu).  Dekker split: Ahi*Bhi + Ahi*Blo + Alo*Bhi.
// TRANSB=true : B is [N,K] row-major (C = A * B^T); false: B is [K,N].
// VEC4: COMPILE-TIME float4 global loads for A (and B when TRANSB); K%4==0 required.
// SYMM: A==B, C symmetric, linear grid over lower-tri tiles, off-diag mirrored.
// Batched over blockIdx.z via zs* strides. ldmatrix fragments + register prefetch.
template<bool TRANSB, bool BIAS_RELU, bool VEC4, bool SYMM>
__global__ __launch_bounds__(256) void gemm_bf16x3(const float* __restrict__ A,
                                                   const float* __restrict__ B,
                                                   const float* __restrict__ bias,
                                                   float* __restrict__ C,
                                                   int M, int N, int K,
                                                   int zsA, int zsB, int zsBias, int zsC)
{
    __shared__ uint32_t sAhi[128 * SSTR];
    __shared__ uint32_t sAlo[128 * SSTR];
    __shared__ uint32_t sBhi[128 * SSTR];
    __shared__ uint32_t sBlo[128 * SSTR];

    A += (size_t)blockIdx.z * zsA;
    B += (size_t)blockIdx.z * zsB;
    if (BIAS_RELU) bias += (size_t)blockIdx.z * zsBias;
    C += (size_t)blockIdx.z * zsC;

    const int tid  = threadIdx.x;
    const int lane = tid & 31;
    const int warp = tid >> 5;
    const int gid  = lane >> 2;
    const int tig  = lane & 3;
    const int wm   = warp >> 2;     // 0..1 -> m offset wm*64
    const int wn   = warp & 3;      // 0..3 -> n offset wn*32

    int mo, no;
    bool mirror = false;
    if (SYMM) {
        int t = blockIdx.x;
        int bi = (int)((sqrtf(8.f * (float)t + 1.f) - 1.f) * 0.5f);
        while ((bi + 1) * (bi + 2) / 2 <= t) bi++;
        while (bi * (bi + 1) / 2 > t) bi--;
        int bj = t - bi * (bi + 1) / 2;
        mo = bi * 128; no = bj * 128;
        mirror = (bi != bj);
    } else {
        mo = blockIdx.y * 128;
        no = blockIdx.x * 128;
    }

    float acc[4][4][4];
#pragma unroll
    for (int i = 0; i < 4; i++)
#pragma unroll
        for (int j = 0; j < 4; j++)
#pragma unroll
            for (int q = 0; q < 4; q++) acc[i][j][q] = 0.f;

    // ldmatrix lane address components (bytes)
    const uint32_t aoff = (uint32_t)((wm * 64 + (lane & 7) + ((lane >> 3) & 1) * 8) * (SSTR * 4)
                                     + ((lane >> 4) & 1) * 16);
    const uint32_t boff = (uint32_t)((wn * 32 + (lane & 7) + ((lane >> 4) & 1) * 8) * (SSTR * 4)
                                     + ((lane >> 3) & 1) * 16);
    const uint32_t baseAhi = smem_u32(sAhi), baseAlo = smem_u32(sAlo);
    const uint32_t baseBhi = smem_u32(sBhi), baseBlo = smem_u32(sBlo);

    auto loadA = [&](int ko, int u) -> float4 {
        int f = u * 256 + tid;
        int r = f >> 3, kq = f & 7;
        int gk = ko + kq * 4;
        float4 v;
        if (VEC4 && gk + 3 < K) {
            v = *reinterpret_cast<const float4*>(&A[(size_t)(mo + r) * K + gk]);
        } else {
            const float* p = &A[(size_t)(mo + r) * K];
            v.x = (gk + 0 < K) ? p[gk + 0] : 0.f;
            v.y = (gk + 1 < K) ? p[gk + 1] : 0.f;
            v.z = (gk + 2 < K) ? p[gk + 2] : 0.f;
            v.w = (gk + 3 < K) ? p[gk + 3] : 0.f;
        }
        return v;
    };
    auto loadB = [&](int ko, int u) -> float4 {
        float4 v;
        if (TRANSB) {
            int f = u * 256 + tid;
            int r = f >> 3, kq = f & 7;
            int gk = ko + kq * 4;
            if (VEC4 && gk + 3 < K) {
                v = *reinterpret_cast<const float4*>(&B[(size_t)(no + r) * K + gk]);
            } else {
                const float* p = &B[(size_t)(no + r) * K];
                v.x = (gk + 0 < K) ? p[gk + 0] : 0.f;
                v.y = (gk + 1 < K) ? p[gk + 1] : 0.f;
                v.z = (gk + 2 < K) ? p[gk + 2] : 0.f;
                v.w = (gk + 3 < K) ? p[gk + 3] : 0.f;
            }
        } else {
            int f = u * 256 + tid;
            int n = f & 127;
            int kq = f >> 7;
            int gk = ko + kq * 4;
            v.x = (gk + 0 < K) ? B[(size_t)(gk + 0) * N + no + n] : 0.f;
            v.y = (gk + 1 < K) ? B[(size_t)(gk + 1) * N + no + n] : 0.f;
            v.z = (gk + 2 < K) ? B[(size_t)(gk + 2) * N + no + n] : 0.f;
            v.w = (gk + 3 < K) ? B[(size_t)(gk + 3) * N + no + n] : 0.f;
        }
        return v;
    };

    float4 va[4], vb[4];
#pragma unroll
    for (int u = 0; u < 4; u++) { va[u] = loadA(0, u); vb[u] = loadB(0, u); }

    for (int ko = 0; ko < K; ko += 32) {
#pragma unroll
        for (int u = 0; u < 4; u++) {
            int f = u * 256 + tid;
            uint32_t h0, h1, l0, l1;
            {   // A: [row][pair]
                int r = f >> 3, kq = f & 7;
                split4(va[u], h0, h1, l0, l1);
                int w = r * SSTR + kq * 2;
                sAhi[w] = h0; sAhi[w + 1] = h1;
                sAlo[w] = l0; sAlo[w + 1] = l1;
            }
            {   // B: [n][pair]
                int r, kq;
                if (TRANSB) { r = f >> 3; kq = f & 7; }
                else        { r = f & 127; kq = f >> 7; }
                split4(vb[u], h0, h1, l0, l1);
                int w = r * SSTR + kq * 2;
                sBhi[w] = h0; sBhi[w + 1] = h1;
                sBlo[w] = l0; sBlo[w + 1] = l1;
            }
        }
        __syncthreads();

        const int kn = ko + 32;
        if (kn < K) {
#pragma unroll
            for (int u = 0; u < 4; u++) { va[u] = loadA(kn, u); vb[u] = loadB(kn, u); }
        }

#pragma unroll
        for (int ks = 0; ks < 2; ks++) {
            const uint32_t kb = (uint32_t)(ks * 32);
            uint32_t bhi[4][2], blo[4][2];
#pragma unroll
            for (int p = 0; p < 2; p++) {
                LDSM_X4(bhi[2 * p][0], bhi[2 * p][1], bhi[2 * p + 1][0], bhi[2 * p + 1][1],
                        baseBhi + boff + (uint32_t)(p * 16 * SSTR * 4) + kb);
                LDSM_X4(blo[2 * p][0], blo[2 * p][1], blo[2 * p + 1][0], blo[2 * p + 1][1],
                        baseBlo + boff + (uint32_t)(p * 16 * SSTR * 4) + kb);
            }
#pragma unroll
            for (int i = 0; i < 4; i++) {
                uint32_t ahi[4], alo[4];
                LDSM_X4(ahi[0], ahi[1], ahi[2], ahi[3],
                        baseAhi + aoff + (uint32_t)(i * 16 * SSTR * 4) + kb);
                LDSM_X4(alo[0], alo[1], alo[2], alo[3],
                        baseAlo + aoff + (uint32_t)(i * 16 * SSTR * 4) + kb);
#pragma unroll
                for (int j = 0; j < 4; j++) {
                    MMA_BF16(acc[i][j], ahi, bhi[j]);
                    MMA_BF16(acc[i][j], ahi, blo[j]);
                    MMA_BF16(acc[i][j], alo, bhi[j]);
                }
            }
        }
        __syncthreads();
    }

    // ---- epilogue
#pragma unroll
    for (int i = 0; i < 4; i++) {
        const int r0 = mo + wm * 64 + i * 16 + gid;
#pragma unroll
        for (int j = 0; j < 4; j++) {
            const int c = no + wn * 32 + j * 8 + tig * 2;
            float v0 = acc[i][j][0], v1 = acc[i][j][1];
            float v2 = acc[i][j][2], v3 = acc[i][j][3];
            if (BIAS_RELU) {
                const float b0 = bias[c], b1 = bias[c + 1];
                v0 = fmaxf(v0 + b0, 0.f); v1 = fmaxf(v1 + b1, 0.f);
                v2 = fmaxf(v2 + b0, 0.f); v3 = fmaxf(v3 + b1, 0.f);
            }
            *reinterpret_cast<float2*>(&C[(size_t)r0 * N + c])       = make_float2(v0, v1);
            *reinterpret_cast<float2*>(&C[(size_t)(r0 + 8) * N + c]) = make_float2(v2, v3);
            if (SYMM && mirror) {
                C[(size_t)c * N + r0]           = v0;
                C[(size_t)(c + 1) * N + r0]     = v1;
                C[(size_t)c * N + r0 + 8]       = v2;
                C[(size_t)(c + 1) * N + r0 + 8] = v3;
            }
        }
    }
}

// ---------------- BatchNorm stats (two stage, deterministic, z-batched) ----------
__global__ void bn_colpart(void)
{
    const int z = blockIdx.z;
    const float* t = g_t + (size_t)z * NH;
    float* part = g_part + (size_t)z * 2 * 64 * HID;
    const int c = threadIdx.x;
    const int r0 = blockIdx.x * 128;
    float s = 0.f, s2 = 0.f;
    for (int r = r0; r < r0 + 128; r++) {
        float v = t[(size_t)r * HID + c];
        s += v; s2 += v * v;
    }
    part[blockIdx.x * HID + c] = s;
    part[64 * HID + blockIdx.x * HID + c] = s2;
}

__global__ void bn_colfinal(const float* __restrict__ gam, const float* __restrict__ bet)
{
    const int z = blockIdx.z;
    const float* part = g_part + (size_t)z * 2 * 64 * HID;
    const int c = threadIdx.x;
    float s = 0.f, s2 = 0.f;
    for (int b = 0; b < 64; b++) {
        s  += part[b * HID + c];
        s2 += part[64 * HID + b * HID + c];
    }
    const float mu = s * (1.f / N_NODES);
    float var = s2 * (1.f / N_NODES) - mu * mu;
    const float a = gam[z * HID + c] * rsqrtf(var + 1e-5f);
    g_bna[z * HID + c] = a;
    g_bnc[z * HID + c] = bet[z * HID + c] - mu * a;
}

__global__ __launch_bounds__(256) void bn_apply_rownorm(void)
{
    const int z = blockIdx.z;
    const float* t = g_t + (size_t)z * NH;
    float* feat = g_feat + (size_t)z * NH;
    float* fn   = g_fn   + (size_t)z * NH;
    const int tid = threadIdx.x;
    const int warp = tid >> 5, lane = tid & 31;
    const int row = blockIdx.x * 8 + warp;
    float v[8];
    float sq = 0.f;
#pragma unroll
    for (int u = 0; u < 8; u++) {
        int c = lane + 32 * u;
        float x = g_bna[z * HID + c] * t[(size_t)row * HID + c] + g_bnc[z * HID + c];
        v[u] = x; sq += x * x;
    }
#pragma unroll
    for (int s = 16; s; s >>= 1) sq += __shfl_xor_sync(0xffffffffu, sq, s);
    const float norm = sqrtf(sq);
    const float inv = 1.f / fmaxf(norm, 1e-12f);
#pragma unroll
    for (int u = 0; u < 8; u++) {
        int c = lane + 32 * u;
        feat[(size_t)row * HID + c] = v[u];
        fn[(size_t)row * HID + c]   = v[u] * inv;
    }
}

// ---------------- top-(K+1) per row + sparse adjacency build ----------------------
// Register-safe hierarchical merge: ALL per-thread list accesses use compile-time
// indices (arrays stay in registers). Per round: unrolled 11-way argmax ->
// warp shfl argmax -> winner invalidated via unrolled index compare.
// Tie-break everywhere: higher value wins; equal value -> lower index wins.
__global__ __launch_bounds__(256) void topk_adj(int* __restrict__ aidx,
                                                float* __restrict__ aw)
{
    const int row = blockIdx.x;
    const int tid = threadIdx.x;
    const int lane = tid & 31;
    const int warp = tid >> 5;
    const float* __restrict__ srow = g_sim + (size_t)row * N_NODES;

    float lv[TOPK]; int li[TOPK];
#pragma unroll
    for (int k = 0; k < TOPK; k++) { lv[k] = -FLT_MAX; li[k] = 0x7FFFFFFF; }

    for (int j = tid; j < N_NODES; j += 256) {
        float v = srow[j];
        if (v > lv[TOPK - 1]) {
            lv[TOPK - 1] = v; li[TOPK - 1] = j;
#pragma unroll
            for (int k = TOPK - 1; k > 0; k--) {
                if (lv[k] > lv[k - 1]) {
                    float tv = lv[k]; lv[k] = lv[k - 1]; lv[k - 1] = tv;
                    int   ti = li[k]; li[k] = li[k - 1]; li[k - 1] = ti;
                } else break;
            }
        }
    }

    // ---- stage 1: intra-warp merge, register-resident (no dynamic indexing)
    __shared__ float wvv[8 * TOPK];
    __shared__ int   wvi[8 * TOPK];
#pragma unroll
    for (int r = 0; r < TOPK; r++) {
        // thread-local best (unrolled; compile-time indices only)
        float bv = lv[0]; int bi_ = li[0];
#pragma unroll
        for (int k = 1; k < TOPK; k++) {
            if (lv[k] > bv || (lv[k] == bv && li[k] < bi_)) { bv = lv[k]; bi_ = li[k]; }
        }
        // warp argmax
        float mv = bv; int mi = bi_;
#pragma unroll
        for (int s = 16; s; s >>= 1) {
            float ov = __shfl_xor_sync(0xffffffffu, mv, s);
            int   oi = __shfl_xor_sync(0xffffffffu, mi, s);
            if (ov > mv || (ov == mv && oi < mi)) { mv = ov; mi = oi; }
        }
        if (lane == 0) { wvv[warp * TOPK + r] = mv; wvi[warp * TOPK + r] = mi; }
        // invalidate consumed entry (indices unique across warp -> at most one hit)
#pragma unroll
        for (int k = 0; k < TOPK; k++) {
            if (li[k] == mi) { lv[k] = -FLT_MAX; li[k] = 0x7FFFFFFF; }
        }
    }
    __syncthreads();

    // ---- stage 2: warp 0 merges 8 sorted lists (lane j < 8 owns list j;
    //      dynamic p indexes SHARED memory -> no register spill)
    if (warp == 0) {
        int p = 0;
        float cand = -FLT_MAX; int ci = 0x7FFFFFFF;
        if (lane < 8) { cand = wvv[lane * TOPK]; ci = wvi[lane * TOPK]; }
        float topv[TOPK]; int topi[TOPK];   // only read with compile-time indices
#pragma unroll
        for (int r = 0; r < TOPK; r++) {
            float mv = cand; int mi = ci;
#pragma unroll
            for (int s = 16; s; s >>= 1) {
                float ov = __shfl_xor_sync(0xffffffffu, mv, s);
                int   oi = __shfl_xor_sync(0xffffffffu, mi, s);
                if (ov > mv || (ov == mv && oi < mi)) { mv = ov; mi = oi; }
            }
            topv[r] = mv; topi[r] = mi;
            if (lane < 8 && ci == mi) {
                p++;
                if (p < TOPK) { cand = wvv[lane * TOPK + p]; ci = wvi[lane * TOPK + p]; }
                else          { cand = -FLT_MAX; ci = 0x7FFFFFFF; }
            }
        }

        if (lane == 0) {
            float diag = 1.0f;
            float wv[TOPK]; int wi[TOPK]; int cnt = 0;
#pragma unroll
            for (int k = 1; k < TOPK; k++) {
                if (topi[k] == row) diag += topv[k];
                else { wv[cnt] = topv[k]; wi[cnt] = topi[k]; cnt++; }
            }
            float rs = fabsf(diag);
            for (int k = 0; k < cnt; k++) rs += fabsf(wv[k]);
            rs = fmaxf(rs, 1e-12f);
            const float inv = 1.f / rs;
            aidx[row * TOPK + 0] = row;
            aw[row * TOPK + 0]   = diag * inv;
            for (int k = 0; k < cnt; k++) {
                aidx[row * TOPK + 1 + k] = wi[k];
                aw[row * TOPK + 1 + k]   = wv[k] * inv;
            }
            for (int k = cnt; k < TOPK - 1; k++) {
                aidx[row * TOPK + 1 + k] = row;
                aw[row * TOPK + 1 + k]   = 0.f;
            }
        }
    }
}

// ---------------- sparse adj @ t + bias, leaky(0.25)  (z-batched) ----------------
__global__ void spmm_leaky(const float* __restrict__ t,
                           const float* __restrict__ bias,
                           float* __restrict__ out)
{
    const int z = blockIdx.z;
    const float* tz = t + (size_t)z * NH;
    const float* bz = bias + (size_t)z * HID;
    float* oz = out + (size_t)z * NH;
    const int* ai = g_adj_idx + (size_t)z * N_NODES * TOPK;
    const float* aw = g_adj_w + (size_t)z * N_NODES * TOPK;

    const int row = blockIdx.x;
    const int c = threadIdx.x;
    float acc = bz[c];
#pragma unroll
    for (int k = 0; k < TOPK; k++) {
        int   j = ai[row * TOPK + k];
        float w = aw[row * TOPK + k];
        acc += w * tz[(size_t)j * HID + c];
    }
    oz[(size_t)row * HID + c] = (acc >= 0.f) ? acc : 0.25f * acc;
}

// ---------------- classifier (z-batched): logits = h @ W[256,5] + b --------------
__global__ __launch_bounds__(256) void clf_kernel(const float* __restrict__ h,
                                                  const float* __restrict__ W,
                                                  const float* __restrict__ b)
{
    const int z = blockIdx.z;
    const float* hz = h + (size_t)z * NH;
    const float* Wz = W + (size_t)z * HID * NCLS;
    const float* bz = b + (size_t)z * NCLS;
    float* oz = g_logits + (size_t)z * N_NODES * NCLS;

    __shared__ float Ws[HID * NCLS];
    const int tid = threadIdx.x;
    for (int i = tid; i < HID * NCLS; i += 256) Ws[i] = Wz[i];
    __syncthreads();
    const int warp = tid >> 5, lane = tid & 31;
    const int row = blockIdx.x * 8 + warp;
    float hv[8];
#pragma unroll
    for (int u = 0; u < 8; u++) hv[u] = hz[(size_t)row * HID + lane + 32 * u];
#pragma unroll
    for (int c = 0; c < NCLS; c++) {
        float acc = 0.f;
#pragma unroll
        for (int u = 0; u < 8; u++) acc += hv[u] * Ws[(lane + 32 * u) * NCLS + c];
#pragma unroll
        for (int s = 16; s; s >>= 1) acc += __shfl_down_sync(0xffffffffu, acc, s);
        if (lane == 0) oz[row * NCLS + c] = acc + bz[c];
    }
}

// ---------------- fusion: softmax(attn), sigmoid mix, 5->128->5 MLP ----------------
__global__ __launch_bounds__(256) void fusion_kernel(const float* __restrict__ attn,
                                                     const float* __restrict__ f1W,
                                                     const float* __restrict__ f1b,
                                                     const float* __restrict__ f2W,
                                                     const float* __restrict__ f2b,
                                                     float* __restrict__ out)
{
    __shared__ float s1[NCLS * 128];
    __shared__ float s2[128 * NCLS];
    __shared__ float sb1[128];
    __shared__ float sb2[NCLS];
    const int tid = threadIdx.x;
    for (int i = tid; i < NCLS * 128; i += 256) s1[i] = f1W[i];
    for (int i = tid; i < 128 * NCLS; i += 256) s2[i] = f2W[i];
    if (tid < 128) sb1[tid] = f1b[tid];
    if (tid < NCLS) sb2[tid] = f2b[tid];
    __syncthreads();

    const int row = blockIdx.x * 256 + tid;
    const float a0 = attn[0], a1 = attn[1], a2 = attn[2];
    const float m = fmaxf(a0, fmaxf(a1, a2));
    const float e0 = expf(a0 - m), e1 = expf(a1 - m), e2 = expf(a2 - m);
    const float invs = 1.f / (e0 + e1 + e2);
    const float w0 = e0 * invs, w1 = e1 * invs, w2 = e2 * invs;

    float fused[NCLS];
#pragma unroll
    for (int c = 0; c < NCLS; c++) {
        float l0 = g_logits[0 * N_NODES * NCLS + row * NCLS + c];
        float l1 = g_logits[1 * N_NODES * NCLS + row * NCLS + c];
        float l2 = g_logits[2 * N_NODES * NCLS + row * NCLS + c];
        fused[c] = w0 / (1.f + expf(-l0)) + w1 / (1.f + expf(-l1)) + w2 / (1.f + expf(-l2));
    }
    float o[NCLS];
#pragma unroll
    for (int c = 0; c < NCLS; c++) o[c] = sb2[c];
    for (int j = 0; j < 128; j++) {
        float t = sb1[j];
#pragma unroll
        for (int c = 0; c < NCLS; c++) t += fused[c] * s1[c * 128 + j];
        t = (t >= 0.f) ? t : 0.25f * t;
#pragma unroll
        for (int c = 0; c < NCLS; c++) o[c] += t * s2[j * NCLS + c];
    }
#pragma unroll
    for (int c = 0; c < NCLS; c++) out[(size_t)row * NCLS + c] = o[c];
}

// ---------------- host launcher ----------------
extern "C" void kernel_launch(void* const* d_in, const int* in_sizes, int n_in,
                              void* d_out, int out_size)
{
    (void)n_in; (void)out_size;
    const float* x[3]    = {(const float*)d_in[0], (const float*)d_in[1], (const float*)d_in[2]};
    const float* encW[3] = {(const float*)d_in[3], (const float*)d_in[4], (const float*)d_in[5]};
    const float* enc_b = (const float*)d_in[6];
    const float* bn_g  = (const float*)d_in[7];
    const float* bn_b  = (const float*)d_in[8];
    const float* gc1W  = (const float*)d_in[9];
    const float* gc1b  = (const float*)d_in[10];
    const float* gc2W  = (const float*)d_in[11];
    const float* gc2b  = (const float*)d_in[12];
    const float* clfW  = (const float*)d_in[13];
    const float* clfb  = (const float*)d_in[14];
    const float* attn  = (const float*)d_in[15];
    const float* f1W   = (const float*)d_in[16];
    const float* f1b   = (const float*)d_in[17];
    const float* f2W   = (const float*)d_in[18];
    const float* f2b   = (const float*)d_in[19];

    float *p_sim, *p_t, *p_feat, *p_fn, *p_h;
    int   *p_aidx; float *p_aw;
    cudaGetSymbolAddress((void**)&p_sim,  g_sim);
    cudaGetSymbolAddress((void**)&p_t,    g_t);
    cudaGetSymbolAddress((void**)&p_feat, g_feat);
    cudaGetSymbolAddress((void**)&p_fn,   g_fn);
    cudaGetSymbolAddress((void**)&p_h,    g_h);
    cudaGetSymbolAddress((void**)&p_aidx, g_adj_idx);
    cudaGetSymbolAddress((void**)&p_aw,   g_adj_w);

    const int NTILE = N_NODES / 128;
    const int NSYMM = NTILE * (NTILE + 1) / 2;   // 2080

    // ---- encoders (separate launches, compile-time VEC4 selection) ----
    for (int i = 0; i < 3; i++) {
        const int Kenc = in_sizes[i] / N_NODES;
        dim3 grid(HID / 128, N_NODES / 128, 1);
        if ((Kenc & 3) == 0)
            gemm_bf16x3<false, true, true, false><<<grid, 256>>>(x[i], encW[i], enc_b + i * HID,
                p_t + (size_t)i * NH, N_NODES, HID, Kenc, 0, 0, 0, 0);
        else
            gemm_bf16x3<false, true, false, false><<<grid, 256>>>(x[i], encW[i], enc_b + i * HID,
                p_t + (size_t)i * NH, N_NODES, HID, Kenc, 0, 0, 0, 0);
    }

    // ---- batchnorm + rownorm (batched over z) ----
    bn_colpart<<<dim3(64, 1, 3), 256>>>();
    bn_colfinal<<<dim3(1, 1, 3), 256>>>(bn_g, bn_b);
    bn_apply_rownorm<<<dim3(N_NODES / 8, 1, 3), 256>>>();

    // ---- per modality: sim (symmetric) + topk (g_sim reused) ----
    for (int i = 0; i < 3; i++) {
        gemm_bf16x3<true, false, true, true><<<dim3(NSYMM, 1, 1), 256>>>(
            p_fn + (size_t)i * NH, p_fn + (size_t)i * NH, nullptr,
            p_sim, N_NODES, N_NODES, HID, 0, 0, 0, 0);
        topk_adj<<<N_NODES, 256>>>(p_aidx + (size_t)i * N_NODES * TOPK,
                                   p_aw   + (size_t)i * N_NODES * TOPK);
    }

    // ---- GCN layers (batched z=3) ----
    {
        dim3 grid(HID / 128, N_NODES / 128, 3);
        gemm_bf16x3<false, false, true, false><<<grid, 256>>>(p_feat, gc1W, nullptr, p_t,
            N_NODES, HID, HID, NH, HID * HID, 0, NH);
        spmm_leaky<<<dim3(N_NODES, 1, 3), HID>>>(p_t, gc1b, p_h);
        gemm_bf16x3<false, false, true, false><<<grid, 256>>>(p_h, gc2W, nullptr, p_t,
            N_NODES, HID, HID, NH, HID * HID, 0, NH);
        spmm_leaky<<<dim3(N_NODES, 1, 3), HID>>>(p_t, gc2b, p_h);
    }

    // ---- classifier (batched) + fusion ----
    clf_kernel<<<dim3(N_NODES / 8, 1, 3), 256>>>(p_h, clfW, clfb);
    fusion_kernel<<<N_NODES / 256, 256>>>(attn, f1W, f1b, f2W, f2b, (float*)d_out);
}

// round 11
// speedup vs baseline: 2.2230x; 1.3873x over previous
#include <cuda_runtime.h>
#include <math.h>
#include <float.h>
#include <stdint.h>

#define N_NODES 8192
#define HID 256
#define NCLS 5
#define TOPK 11   // K+1
#define SSTR 20   // smem row stride in uint32 (bf16-pair) units; 16 pairs + 4 pad
#define NH (N_NODES * HID)

// ---------------- scratch (static device globals; no allocation) ----------------
__device__ float g_sim[(size_t)N_NODES * N_NODES];   // 256 MB (reused per modality)
__device__ float g_t[3 * NH];
__device__ float g_feat[3 * NH];
__device__ float g_fn[3 * NH];
__device__ float g_h[3 * NH];
__device__ float g_part[3 * 2 * 64 * HID];
__device__ float g_bna[3 * HID];
__device__ float g_bnc[3 * HID];
__device__ int   g_adj_idx[3 * N_NODES * TOPK];
__device__ float g_adj_w[3 * N_NODES * TOPK];
__device__ float g_logits[3 * N_NODES * NCLS];

// pack two floats to bf16x2 (low = x, high = y), round-to-nearest
__device__ __forceinline__ uint32_t pack_bf16(float x, float y)
{
    uint32_t r;
    asm("cvt.rn.bf16x2.f32 %0, %1, %2;" : "=r"(r) : "f"(y), "f"(x));
    return r;
}
__device__ __forceinline__ float bf16lo_f(uint32_t p) { return __uint_as_float(p << 16); }
__device__ __forceinline__ float bf16hi_f(uint32_t p) { return __uint_as_float(p & 0xFFFF0000u); }

__device__ __forceinline__ void split4(float4 v, uint32_t& h0, uint32_t& h1,
                                       uint32_t& l0, uint32_t& l1)
{
    h0 = pack_bf16(v.x, v.y);
    h1 = pack_bf16(v.z, v.w);
    l0 = pack_bf16(v.x - bf16lo_f(h0), v.y - bf16hi_f(h0));
    l1 = pack_bf16(v.z - bf16lo_f(h1), v.w - bf16hi_f(h1));
}

#define MMA_BF16(C, A, B) \
    asm volatile( \
        "mma.sync.aligned.m16n8k16.row.col.f32.bf16.bf16.f32 " \
        "{%0,%1,%2,%3}, {%4,%5,%6,%7}, {%8,%9}, {%0,%1,%2,%3};\n" \
        : "+f"((C)[0]), "+f"((C)[1]), "+f"((C)[2]), "+f"((C)[3]) \
        : "r"((A)[0]), "r"((A)[1]), "r"((A)[2]), "r"((A)[3]), \
          "r"((B)[0]), "r"((B)[1]))

#define LDSM_X4(r0, r1, r2, r3, addr) \
    asm volatile("ldmatrix.sync.aligned.m8n8.x4.shared.b16 {%0,%1,%2,%3}, [%4];" \
        : "=r"(r0), "=r"(r1), "=r"(r2), "=r"(r3) : "r"(addr))

__device__ __forceinline__ uint32_t smem_u32(const void* p)
{
    return (uint32_t)__cvta_generic_to_shared(p);
}

// ---------------- bf16x3 split-precision tensor-core GEMM ------------------------
// C[M,N] = A[M,K] * op(B) (+bias,+relu).  Dekker split: Ahi*Bhi + Ahi*Blo + Alo*Bhi.
// TRANSB=true : B is [N,K] row-major (C = A * B^T); false: B is [K,N].
// VEC4: COMPILE-TIME float4 global loads for A (and B when TRANSB); K%4==0 required.
// SYMM: A==B, C symmetric, linear grid over lower-tri tiles, off-diag mirrored.
// Batched over blockIdx.z via zs* strides. ldmatrix fragments + register prefetch.
template<bool TRANSB, bool BIAS_RELU, bool VEC4, bool SYMM>
__global__ __launch_bounds__(256) void gemm_bf16x3(const float* __restrict__ A,
                                                   const float* __restrict__ B,
                                                   const float* __restrict__ bias,
                                                   float* __restrict__ C,
                                                   int M, int N, int K,
                                                   int zsA, int zsB, int zsBias, int zsC)
{
    __shared__ uint32_t sAhi[128 * SSTR];
    __shared__ uint32_t sAlo[128 * SSTR];
    __shared__ uint32_t sBhi[128 * SSTR];
    __shared__ uint32_t sBlo[128 * SSTR];

    A += (size_t)blockIdx.z * zsA;
    B += (size_t)blockIdx.z * zsB;
    if (BIAS_RELU) bias += (size_t)blockIdx.z * zsBias;
    C += (size_t)blockIdx.z * zsC;

    const int tid  = threadIdx.x;
    const int lane = tid & 31;
    const int warp = tid >> 5;
    const int gid  = lane >> 2;
    const int tig  = lane & 3;
    const int wm   = warp >> 2;     // 0..1 -> m offset wm*64
    const int wn   = warp & 3;      // 0..3 -> n offset wn*32

    int mo, no;
    bool mirror = false;
    if (SYMM) {
        int t = blockIdx.x;
        int bi = (int)((sqrtf(8.f * (float)t + 1.f) - 1.f) * 0.5f);
        while ((bi + 1) * (bi + 2) / 2 <= t) bi++;
        while (bi * (bi + 1) / 2 > t) bi--;
        int bj = t - bi * (bi + 1) / 2;
        mo = bi * 128; no = bj * 128;
        mirror = (bi != bj);
    } else {
        mo = blockIdx.y * 128;
        no = blockIdx.x * 128;
    }

    float acc[4][4][4];
#pragma unroll
    for (int i = 0; i < 4; i++)
#pragma unroll
        for (int j = 0; j < 4; j++)
#pragma unroll
            for (int q = 0; q < 4; q++) acc[i][j][q] = 0.f;

    // ldmatrix lane address components (bytes)
    const uint32_t aoff = (uint32_t)((wm * 64 + (lane & 7) + ((lane >> 3) & 1) * 8) * (SSTR * 4)
                                     + ((lane >> 4) & 1) * 16);
    const uint32_t boff = (uint32_t)((wn * 32 + (lane & 7) + ((lane >> 4) & 1) * 8) * (SSTR * 4)
                                     + ((lane >> 3) & 1) * 16);
    const uint32_t baseAhi = smem_u32(sAhi), baseAlo = smem_u32(sAlo);
    const uint32_t baseBhi = smem_u32(sBhi), baseBlo = smem_u32(sBlo);

    auto loadA = [&](int ko, int u) -> float4 {
        int f = u * 256 + tid;
        int r = f >> 3, kq = f & 7;
        int gk = ko + kq * 4;
        float4 v;
        if (VEC4 && gk + 3 < K) {
            v = *reinterpret_cast<const float4*>(&A[(size_t)(mo + r) * K + gk]);
        } else {
            const float* p = &A[(size_t)(mo + r) * K];
            v.x = (gk + 0 < K) ? p[gk + 0] : 0.f;
            v.y = (gk + 1 < K) ? p[gk + 1] : 0.f;
            v.z = (gk + 2 < K) ? p[gk + 2] : 0.f;
            v.w = (gk + 3 < K) ? p[gk + 3] : 0.f;
        }
        return v;
    };
    auto loadB = [&](int ko, int u) -> float4 {
        float4 v;
        if (TRANSB) {
            int f = u * 256 + tid;
            int r = f >> 3, kq = f & 7;
            int gk = ko + kq * 4;
            if (VEC4 && gk + 3 < K) {
                v = *reinterpret_cast<const float4*>(&B[(size_t)(no + r) * K + gk]);
            } else {
                const float* p = &B[(size_t)(no + r) * K];
                v.x = (gk + 0 < K) ? p[gk + 0] : 0.f;
                v.y = (gk + 1 < K) ? p[gk + 1] : 0.f;
                v.z = (gk + 2 < K) ? p[gk + 2] : 0.f;
                v.w = (gk + 3 < K) ? p[gk + 3] : 0.f;
            }
        } else {
            int f = u * 256 + tid;
            int n = f & 127;
            int kq = f >> 7;
            int gk = ko + kq * 4;
            v.x = (gk + 0 < K) ? B[(size_t)(gk + 0) * N + no + n] : 0.f;
            v.y = (gk + 1 < K) ? B[(size_t)(gk + 1) * N + no + n] : 0.f;
            v.z = (gk + 2 < K) ? B[(size_t)(gk + 2) * N + no + n] : 0.f;
            v.w = (gk + 3 < K) ? B[(size_t)(gk + 3) * N + no + n] : 0.f;
        }
        return v;
    };

    float4 va[4], vb[4];
#pragma unroll
    for (int u = 0; u < 4; u++) { va[u] = loadA(0, u); vb[u] = loadB(0, u); }

    for (int ko = 0; ko < K; ko += 32) {
#pragma unroll
        for (int u = 0; u < 4; u++) {
            int f = u * 256 + tid;
            uint32_t h0, h1, l0, l1;
            {   // A: [row][pair]
                int r = f >> 3, kq = f & 7;
                split4(va[u], h0, h1, l0, l1);
                int w = r * SSTR + kq * 2;
                sAhi[w] = h0; sAhi[w + 1] = h1;
                sAlo[w] = l0; sAlo[w + 1] = l1;
            }
            {   // B: [n][pair]
                int r, kq;
                if (TRANSB) { r = f >> 3; kq = f & 7; }
                else        { r = f & 127; kq = f >> 7; }
                split4(vb[u], h0, h1, l0, l1);
                int w = r * SSTR + kq * 2;
                sBhi[w] = h0; sBhi[w + 1] = h1;
                sBlo[w] = l0; sBlo[w + 1] = l1;
            }
        }
        __syncthreads();

        const int kn = ko + 32;
        if (kn < K) {
#pragma unroll
            for (int u = 0; u < 4; u++) { va[u] = loadA(kn, u); vb[u] = loadB(kn, u); }
        }

#pragma unroll
        for (int ks = 0; ks < 2; ks++) {
            const uint32_t kb = (uint32_t)(ks * 32);
            uint32_t bhi[4][2], blo[4][2];
#pragma unroll
            for (int p = 0; p < 2; p++) {
                LDSM_X4(bhi[2 * p][0], bhi[2 * p][1], bhi[2 * p + 1][0], bhi[2 * p + 1][1],
                        baseBhi + boff + (uint32_t)(p * 16 * SSTR * 4) + kb);
                LDSM_X4(blo[2 * p][0], blo[2 * p][1], blo[2 * p + 1][0], blo[2 * p + 1][1],
                        baseBlo + boff + (uint32_t)(p * 16 * SSTR * 4) + kb);
            }
#pragma unroll
            for (int i = 0; i < 4; i++) {
                uint32_t ahi[4], alo[4];
                LDSM_X4(ahi[0], ahi[1], ahi[2], ahi[3],
                        baseAhi + aoff + (uint32_t)(i * 16 * SSTR * 4) + kb);
                LDSM_X4(alo[0], alo[1], alo[2], alo[3],
                        baseAlo + aoff + (uint32_t)(i * 16 * SSTR * 4) + kb);
#pragma unroll
                for (int j = 0; j < 4; j++) {
                    MMA_BF16(acc[i][j], ahi, bhi[j]);
                    MMA_BF16(acc[i][j], ahi, blo[j]);
                    MMA_BF16(acc[i][j], alo, bhi[j]);
                }
            }
        }
        __syncthreads();
    }

    // ---- epilogue
#pragma unroll
    for (int i = 0; i < 4; i++) {
        const int r0 = mo + wm * 64 + i * 16 + gid;
#pragma unroll
        for (int j = 0; j < 4; j++) {
            const int c = no + wn * 32 + j * 8 + tig * 2;
            float v0 = acc[i][j][0], v1 = acc[i][j][1];
            float v2 = acc[i][j][2], v3 = acc[i][j][3];
            if (BIAS_RELU) {
                const float b0 = bias[c], b1 = bias[c + 1];
                v0 = fmaxf(v0 + b0, 0.f); v1 = fmaxf(v1 + b1, 0.f);
                v2 = fmaxf(v2 + b0, 0.f); v3 = fmaxf(v3 + b1, 0.f);
            }
            *reinterpret_cast<float2*>(&C[(size_t)r0 * N + c])       = make_float2(v0, v1);
            *reinterpret_cast<float2*>(&C[(size_t)(r0 + 8) * N + c]) = make_float2(v2, v3);
            if (SYMM && mirror) {
                C[(size_t)c * N + r0]           = v0;
                C[(size_t)(c + 1) * N + r0]     = v1;
                C[(size_t)c * N + r0 + 8]       = v2;
                C[(size_t)(c + 1) * N + r0 + 8] = v3;
            }
        }
    }
}

// ---------------- BatchNorm stats (two stage, deterministic, z-batched) ----------
__global__ void bn_colpart(void)
{
    const int z = blockIdx.z;
    const float* t = g_t + (size_t)z * NH;
    float* part = g_part + (size_t)z * 2 * 64 * HID;
    const int c = threadIdx.x;
    const int r0 = blockIdx.x * 128;
    float s = 0.f, s2 = 0.f;
    for (int r = r0; r < r0 + 128; r++) {
        float v = t[(size_t)r * HID + c];
        s += v; s2 += v * v;
    }
    part[blockIdx.x * HID + c] = s;
    part[64 * HID + blockIdx.x * HID + c] = s2;
}

__global__ void bn_colfinal(const float* __restrict__ gam, const float* __restrict__ bet)
{
    const int z = blockIdx.z;
    const float* part = g_part + (size_t)z * 2 * 64 * HID;
    const int c = threadIdx.x;
    float s = 0.f, s2 = 0.f;
    for (int b = 0; b < 64; b++) {
        s  += part[b * HID + c];
        s2 += part[64 * HID + b * HID + c];
    }
    const float mu = s * (1.f / N_NODES);
    float var = s2 * (1.f / N_NODES) - mu * mu;
    const float a = gam[z * HID + c] * rsqrtf(var + 1e-5f);
    g_bna[z * HID + c] = a;
    g_bnc[z * HID + c] = bet[z * HID + c] - mu * a;
}

__global__ __launch_bounds__(256) void bn_apply_rownorm(void)
{
    const int z = blockIdx.z;
    const float* t = g_t + (size_t)z * NH;
    float* feat = g_feat + (size_t)z * NH;
    float* fn   = g_fn   + (size_t)z * NH;
    const int tid = threadIdx.x;
    const int warp = tid >> 5, lane = tid & 31;
    const int row = blockIdx.x * 8 + warp;
    float v[8];
    float sq = 0.f;
#pragma unroll
    for (int u = 0; u < 8; u++) {
        int c = lane + 32 * u;
        float x = g_bna[z * HID + c] * t[(size_t)row * HID + c] + g_bnc[z * HID + c];
        v[u] = x; sq += x * x;
    }
#pragma unroll
    for (int s = 16; s; s >>= 1) sq += __shfl_xor_sync(0xffffffffu, sq, s);
    const float norm = sqrtf(sq);
    const float inv = 1.f / fmaxf(norm, 1e-12f);
#pragma unroll
    for (int u = 0; u < 8; u++) {
        int c = lane + 32 * u;
        feat[(size_t)row * HID + c] = v[u];
        fn[(size_t)row * HID + c]   = v[u] * inv;
    }
}

// ---------------- top-(K+1) per row + sparse adjacency build ----------------------
// EXACT R7 tree-merge structure (empirically fastest). Only change vs R7: the scan
// uses float4 loads (partition-independent: merge tie-breaks on (value, lower idx),
// per-thread insertion uses strict > so equal-value later(=larger) index is dropped,
// and the winner-advance relies only on global index uniqueness).
__global__ __launch_bounds__(256) void topk_adj(int* __restrict__ aidx,
                                                float* __restrict__ aw)
{
    const int row = blockIdx.x;
    const int tid = threadIdx.x;
    const float* __restrict__ srow = g_sim + (size_t)row * N_NODES;

    float lv[TOPK]; int li[TOPK];
#pragma unroll
    for (int k = 0; k < TOPK; k++) { lv[k] = -FLT_MAX; li[k] = 0x7FFFFFFF; }

    auto insert = [&](float v, int j) {
        if (v > lv[TOPK - 1]) {
            lv[TOPK - 1] = v; li[TOPK - 1] = j;
#pragma unroll
            for (int k = TOPK - 1; k > 0; k--) {
                if (lv[k] > lv[k - 1]) {
                    float tv = lv[k]; lv[k] = lv[k - 1]; lv[k - 1] = tv;
                    int   ti = li[k]; li[k] = li[k - 1]; li[k - 1] = ti;
                } else break;
            }
        }
    };

    // float4 scan: thread t owns j in {4t..4t+3} + q*1024 (j increasing per thread)
    for (int j4 = tid * 4; j4 < N_NODES; j4 += 1024) {
        float4 v4 = *reinterpret_cast<const float4*>(&srow[j4]);
        insert(v4.x, j4 + 0);
        insert(v4.y, j4 + 1);
        insert(v4.z, j4 + 2);
        insert(v4.w, j4 + 3);
    }

    __shared__ float cv[256 * TOPK];
    __shared__ int   ci[256 * TOPK];
#pragma unroll
    for (int k = 0; k < TOPK; k++) { cv[tid * TOPK + k] = lv[k]; ci[tid * TOPK + k] = li[k]; }

    __shared__ float rv[256];
    __shared__ int   ri[256];
    __shared__ float topv[TOPK];
    __shared__ int   topi[TOPK];

    int p = 0;
    for (int r = 0; r < TOPK; r++) {
        float mv = (p < TOPK) ? cv[tid * TOPK + p] : -FLT_MAX;
        int   mj = (p < TOPK) ? ci[tid * TOPK + p] : 0x7FFFFFFF;
        rv[tid] = mv; ri[tid] = mj;
        __syncthreads();
        for (int s = 128; s > 0; s >>= 1) {
            if (tid < s) {
                float ov = rv[tid + s]; int oj = ri[tid + s];
                if (ov > rv[tid] || (ov == rv[tid] && oj < ri[tid])) { rv[tid] = ov; ri[tid] = oj; }
            }
            __syncthreads();
        }
        int bj = ri[0];
        if (tid == 0) { topv[r] = rv[0]; topi[r] = bj; }
        if (mj == bj) p++;           // j unique per candidate -> winner advances
        __syncthreads();
    }

    if (tid == 0) {
        float diag = 1.0f;
        float wv[TOPK]; int wi[TOPK]; int cnt = 0;
        for (int k = 1; k < TOPK; k++) {
            if (topi[k] == row) diag += topv[k];
            else { wv[cnt] = topv[k]; wi[cnt] = topi[k]; cnt++; }
        }
        float rs = fabsf(diag);
        for (int k = 0; k < cnt; k++) rs += fabsf(wv[k]);
        rs = fmaxf(rs, 1e-12f);
        const float inv = 1.f / rs;
        aidx[row * TOPK + 0] = row;
        aw[row * TOPK + 0]   = diag * inv;
        for (int k = 0; k < cnt; k++) {
            aidx[row * TOPK + 1 + k] = wi[k];
            aw[row * TOPK + 1 + k]   = wv[k] * inv;
        }
        for (int k = cnt; k < TOPK - 1; k++) {
            aidx[row * TOPK + 1 + k] = row;
            aw[row * TOPK + 1 + k]   = 0.f;
        }
    }
}

// ---------------- sparse adj @ t + bias, leaky(0.25)  (z-batched) ----------------
__global__ void spmm_leaky(const float* __restrict__ t,
                           const float* __restrict__ bias,
                           float* __restrict__ out)
{
    const int z = blockIdx.z;
    const float* tz = t + (size_t)z * NH;
    const float* bz = bias + (size_t)z * HID;
    float* oz = out + (size_t)z * NH;
    const int* ai = g_adj_idx + (size_t)z * N_NODES * TOPK;
    const float* aw = g_adj_w + (size_t)z * N_NODES * TOPK;

    const int row = blockIdx.x;
    const int c = threadIdx.x;
    float acc = bz[c];
#pragma unroll
    for (int k = 0; k < TOPK; k++) {
        int   j = ai[row * TOPK + k];
        float w = aw[row * TOPK + k];
        acc += w * tz[(size_t)j * HID + c];
    }
    oz[(size_t)row * HID + c] = (acc >= 0.f) ? acc : 0.25f * acc;
}

// ---------------- classifier (z-batched): logits = h @ W[256,5] + b --------------
__global__ __launch_bounds__(256) void clf_kernel(const float* __restrict__ h,
                                                  const float* __restrict__ W,
                                                  const float* __restrict__ b)
{
    const int z = blockIdx.z;
    const float* hz = h + (size_t)z * NH;
    const float* Wz = W + (size_t)z * HID * NCLS;
    const float* bz = b + (size_t)z * NCLS;
    float* oz = g_logits + (size_t)z * N_NODES * NCLS;

    __shared__ float Ws[HID * NCLS];
    const int tid = threadIdx.x;
    for (int i = tid; i < HID * NCLS; i += 256) Ws[i] = Wz[i];
    __syncthreads();
    const int warp = tid >> 5, lane = tid & 31;
    const int row = blockIdx.x * 8 + warp;
    float hv[8];
#pragma unroll
    for (int u = 0; u < 8; u++) hv[u] = hz[(size_t)row * HID + lane + 32 * u];
#pragma unroll
    for (int c = 0; c < NCLS; c++) {
        float acc = 0.f;
#pragma unroll
        for (int u = 0; u < 8; u++) acc += hv[u] * Ws[(lane + 32 * u) * NCLS + c];
#pragma unroll
        for (int s = 16; s; s >>= 1) acc += __shfl_down_sync(0xffffffffu, acc, s);
        if (lane == 0) oz[row * NCLS + c] = acc + bz[c];
    }
}

// ---------------- fusion: softmax(attn), sigmoid mix, 5->128->5 MLP ----------------
__global__ __launch_bounds__(256) void fusion_kernel(const float* __restrict__ attn,
                                                     const float* __restrict__ f1W,
                                                     const float* __restrict__ f1b,
                                                     const float* __restrict__ f2W,
                                                     const float* __restrict__ f2b,
                                                     float* __restrict__ out)
{
    __shared__ float s1[NCLS * 128];
    __shared__ float s2[128 * NCLS];
    __shared__ float sb1[128];
    __shared__ float sb2[NCLS];
    const int tid = threadIdx.x;
    for (int i = tid; i < NCLS * 128; i += 256) s1[i] = f1W[i];
    for (int i = tid; i < 128 * NCLS; i += 256) s2[i] = f2W[i];
    if (tid < 128) sb1[tid] = f1b[tid];
    if (tid < NCLS) sb2[tid] = f2b[tid];
    __syncthreads();

    const int row = blockIdx.x * 256 + tid;
    const float a0 = attn[0], a1 = attn[1], a2 = attn[2];
    const float m = fmaxf(a0, fmaxf(a1, a2));
    const float e0 = expf(a0 - m), e1 = expf(a1 - m), e2 = expf(a2 - m);
    const float invs = 1.f / (e0 + e1 + e2);
    const float w0 = e0 * invs, w1 = e1 * invs, w2 = e2 * invs;

    float fused[NCLS];
#pragma unroll
    for (int c = 0; c < NCLS; c++) {
        float l0 = g_logits[0 * N_NODES * NCLS + row * NCLS + c];
        float l1 = g_logits[1 * N_NODES * NCLS + row * NCLS + c];
        float l2 = g_logits[2 * N_NODES * NCLS + row * NCLS + c];
        fused[c] = w0 / (1.f + expf(-l0)) + w1 / (1.f + expf(-l1)) + w2 / (1.f + expf(-l2));
    }
    float o[NCLS];
#pragma unroll
    for (int c = 0; c < NCLS; c++) o[c] = sb2[c];
    for (int j = 0; j < 128; j++) {
        float t = sb1[j];
#pragma unroll
        for (int c = 0; c < NCLS; c++) t += fused[c] * s1[c * 128 + j];
        t = (t >= 0.f) ? t : 0.25f * t;
#pragma unroll
        for (int c = 0; c < NCLS; c++) o[c] += t * s2[j * NCLS + c];
    }
#pragma unroll
    for (int c = 0; c < NCLS; c++) out[(size_t)row * NCLS + c] = o[c];
}

// ---------------- host launcher ----------------
extern "C" void kernel_launch(void* const* d_in, const int* in_sizes, int n_in,
                              void* d_out, int out_size)
{
    (void)n_in; (void)out_size;
    const float* x[3]    = {(const float*)d_in[0], (const float*)d_in[1], (const float*)d_in[2]};
    const float* encW[3] = {(const float*)d_in[3], (const float*)d_in[4], (const float*)d_in[5]};
    const float* enc_b = (const float*)d_in[6];
    const float* bn_g  = (const float*)d_in[7];
    const float* bn_b  = (const float*)d_in[8];
    const float* gc1W  = (const float*)d_in[9];
    const float* gc1b  = (const float*)d_in[10];
    const float* gc2W  = (const float*)d_in[11];
    const float* gc2b  = (const float*)d_in[12];
    const float* clfW  = (const float*)d_in[13];
    const float* clfb  = (const float*)d_in[14];
    const float* attn  = (const float*)d_in[15];
    const float* f1W   = (const float*)d_in[16];
    const float* f1b   = (const float*)d_in[17];
    const float* f2W   = (const float*)d_in[18];
    const float* f2b   = (const float*)d_in[19];

    float *p_sim, *p_t, *p_feat, *p_fn, *p_h;
    int   *p_aidx; float *p_aw;
    cudaGetSymbolAddress((void**)&p_sim,  g_sim);
    cudaGetSymbolAddress((void**)&p_t,    g_t);
    cudaGetSymbolAddress((void**)&p_feat, g_feat);
    cudaGetSymbolAddress((void**)&p_fn,   g_fn);
    cudaGetSymbolAddress((void**)&p_h,    g_h);
    cudaGetSymbolAddress((void**)&p_aidx, g_adj_idx);
    cudaGetSymbolAddress((void**)&p_aw,   g_adj_w);

    const int NTILE = N_NODES / 128;
    const int NSYMM = NTILE * (NTILE + 1) / 2;   // 2080

    // ---- encoders (separate launches, compile-time VEC4 selection) ----
    for (int i = 0; i < 3; i++) {
        const int Kenc = in_sizes[i] / N_NODES;
        dim3 grid(HID / 128, N_NODES / 128, 1);
        if ((Kenc & 3) == 0)
            gemm_bf16x3<false, true, true, false><<<grid, 256>>>(x[i], encW[i], enc_b + i * HID,
                p_t + (size_t)i * NH, N_NODES, HID, Kenc, 0, 0, 0, 0);
        else
            gemm_bf16x3<false, true, false, false><<<grid, 256>>>(x[i], encW[i], enc_b + i * HID,
                p_t + (size_t)i * NH, N_NODES, HID, Kenc, 0, 0, 0, 0);
    }

    // ---- batchnorm + rownorm (batched over z) ----
    bn_colpart<<<dim3(64, 1, 3), 256>>>();
    bn_colfinal<<<dim3(1, 1, 3), 256>>>(bn_g, bn_b);
    bn_apply_rownorm<<<dim3(N_NODES / 8, 1, 3), 256>>>();

    // ---- per modality: sim (symmetric) + topk (g_sim reused) ----
    for (int i = 0; i < 3; i++) {
        gemm_bf16x3<true, false, true, true><<<dim3(NSYMM, 1, 1), 256>>>(
            p_fn + (size_t)i * NH, p_fn + (size_t)i * NH, nullptr,
            p_sim, N_NODES, N_NODES, HID, 0, 0, 0, 0);
        topk_adj<<<N_NODES, 256>>>(p_aidx + (size_t)i * N_NODES * TOPK,
                                   p_aw   + (size_t)i * N_NODES * TOPK);
    }

    // ---- GCN layers (batched z=3) ----
    {
        dim3 grid(HID / 128, N_NODES / 128, 3);
        gemm_bf16x3<false, false, true, false><<<grid, 256>>>(p_feat, gc1W, nullptr, p_t,
            N_NODES, HID, HID, NH, HID * HID, 0, NH);
        spmm_leaky<<<dim3(N_NODES, 1, 3), HID>>>(p_t, gc1b, p_h);
        gemm_bf16x3<false, false, true, false><<<grid, 256>>>(p_h, gc2W, nullptr, p_t,
            N_NODES, HID, HID, NH, HID * HID, 0, NH);
        spmm_leaky<<<dim3(N_NODES, 1, 3), HID>>>(p_t, gc2b, p_h);
    }

    // ---- classifier (batched) + fusion ----
    clf_kernel<<<dim3(N_NODES / 8, 1, 3), 256>>>(p_h, clfW, clfb);
    fusion_kernel<<<N_NODES / 256, 256>>>(attn, f1W, f1b, f2W, f2b, (float*)d_out);
}